// round 2
// baseline (speedup 1.0000x reference)
#include <cuda_runtime.h>

#define N_NODES 100000
#define N_EDGES 3200000
#define IN_DIM  128
#define HID     64
#define N_GRAPHS 64
#define OUT_DIM 10

// Device-global scratch (no dynamic allocation allowed)
__device__ float g_T [(size_t)N_NODES * HID];   // linear output (pre-SpMM)
__device__ float g_X1[(size_t)N_NODES * HID];
__device__ float g_X2[(size_t)N_NODES * HID];
__device__ float g_X3[(size_t)N_NODES * HID];
__device__ float g_pool[N_GRAPHS * HID];

// ---------------------------------------------------------------------------
// Dense linear: out[i,h] = bias[h] + sum_k in[i,k] * W[h,k]
// Tile: 64 rows x 64 cols (HID==64 covers full width), BK=16, 256 threads,
// 4x4 register microtile per thread.
// ---------------------------------------------------------------------------
template<int K>
__global__ void linear_kernel(const float* __restrict__ in,
                              const float* __restrict__ W,
                              const float* __restrict__ bias,
                              float* __restrict__ out) {
    __shared__ __align__(16) float As[16][68];
    __shared__ __align__(16) float Bs[16][68];

    const int tid = threadIdx.x;          // 0..255
    const int tx  = tid & 15;             // col group
    const int ty  = tid >> 4;             // row group
    const int i0  = blockIdx.x * 64;

    float bj[4];
#pragma unroll
    for (int j = 0; j < 4; j++) bj[j] = bias[(tx << 2) + j];

    float acc[4][4];
#pragma unroll
    for (int i = 0; i < 4; i++)
#pragma unroll
        for (int j = 0; j < 4; j++) acc[i][j] = bj[j];

    const int lm = tid >> 2;              // 0..63: row within tile (also h for W)
    const int lk = (tid & 3) << 2;        // 0,4,8,12
    int grow = i0 + lm;
    if (grow >= N_NODES) grow = N_NODES - 1;   // clamp (stores are guarded)

    const float* inp = in + (size_t)grow * K;
    const float* wp  = W  + (size_t)lm * K;

    for (int k0 = 0; k0 < K; k0 += 16) {
        float4 a = *(const float4*)(inp + k0 + lk);
        float4 w = *(const float4*)(wp  + k0 + lk);
        As[lk + 0][lm] = a.x; As[lk + 1][lm] = a.y;
        As[lk + 2][lm] = a.z; As[lk + 3][lm] = a.w;
        Bs[lk + 0][lm] = w.x; Bs[lk + 1][lm] = w.y;
        Bs[lk + 2][lm] = w.z; Bs[lk + 3][lm] = w.w;
        __syncthreads();
#pragma unroll
        for (int kk = 0; kk < 16; kk++) {
            float4 av = *(const float4*)(&As[kk][ty << 2]);
            float4 bv = *(const float4*)(&Bs[kk][tx << 2]);
            acc[0][0] += av.x * bv.x; acc[0][1] += av.x * bv.y;
            acc[0][2] += av.x * bv.z; acc[0][3] += av.x * bv.w;
            acc[1][0] += av.y * bv.x; acc[1][1] += av.y * bv.y;
            acc[1][2] += av.y * bv.z; acc[1][3] += av.y * bv.w;
            acc[2][0] += av.z * bv.x; acc[2][1] += av.z * bv.y;
            acc[2][2] += av.z * bv.z; acc[2][3] += av.z * bv.w;
            acc[3][0] += av.w * bv.x; acc[3][1] += av.w * bv.y;
            acc[3][2] += av.w * bv.z; acc[3][3] += av.w * bv.w;
        }
        __syncthreads();
    }

#pragma unroll
    for (int i = 0; i < 4; i++) {
        int r = i0 + (ty << 2) + i;
        if (r < N_NODES) {
            float4 v = make_float4(acc[i][0], acc[i][1], acc[i][2], acc[i][3]);
            *(float4*)(out + (size_t)r * HID + (tx << 2)) = v;
        }
    }
}

// ---------------------------------------------------------------------------
// SpMM scatter: out[rows[e], :] += vals[e] * H[cols[e], :]
// 4 threads per edge, each handles 16 floats (4x float4) with vectorized RED.
// ---------------------------------------------------------------------------
__global__ void spmm_kernel(const int* __restrict__ rows,
                            const int* __restrict__ cols,
                            const float* __restrict__ vals,
                            const float* __restrict__ H,
                            float* __restrict__ out) {
    int gid = blockIdx.x * blockDim.x + threadIdx.x;
    int e = gid >> 2;
    if (e >= N_EDGES) return;
    int p = gid & 3;

    int c = cols[e];
    int r = rows[e];
    float v = vals[e];

    const float4* src = (const float4*)(H + (size_t)c * HID) + (p << 2);
    float4* dst = (float4*)(out + (size_t)r * HID) + (p << 2);
#pragma unroll
    for (int j = 0; j < 4; j++) {
        float4 x = src[j];
        atomicAdd(dst + j, make_float4(x.x * v, x.y * v, x.z * v, x.w * v));
    }
}

// ---------------------------------------------------------------------------
// In-place ReLU over N_NODES*HID floats (as float4)
// ---------------------------------------------------------------------------
__global__ void relu_kernel(float* __restrict__ x) {
    int gid = blockIdx.x * blockDim.x + threadIdx.x;
    if (gid >= N_NODES * HID / 4) return;
    float4 v = ((float4*)x)[gid];
    v.x = fmaxf(v.x, 0.0f);
    v.y = fmaxf(v.y, 0.0f);
    v.z = fmaxf(v.z, 0.0f);
    v.w = fmaxf(v.w, 0.0f);
    ((float4*)x)[gid] = v;
}

// ---------------------------------------------------------------------------
// Global mean pool (sums via atomics; counts computed later by binary search)
// One thread per (node, quarter-row).
// ---------------------------------------------------------------------------
__global__ void pool_kernel(const float* __restrict__ X1,
                            const float* __restrict__ X2,
                            const float* __restrict__ X3,
                            const int* __restrict__ batch,
                            float* __restrict__ pool) {
    int gid = blockIdx.x * blockDim.x + threadIdx.x;
    if (gid >= N_NODES * 16) return;
    int i = gid >> 4;
    int q = gid & 15;
    int g = batch[i];

    float4 a = ((const float4*)X1)[gid];
    float4 b = ((const float4*)X2)[gid];
    float4 c = ((const float4*)X3)[gid];
    const float s = 1.0f / 3.0f;
    float4 v = make_float4((a.x + b.x + c.x) * s,
                           (a.y + b.y + c.y) * s,
                           (a.z + b.z + c.z) * s,
                           (a.w + b.w + c.w) * s);
    atomicAdd((float4*)(pool + (size_t)g * HID) + q, v);
}

// ---------------------------------------------------------------------------
// Head: per-graph mean (count via binary search on sorted batch), linear,
// softmax. One thread per graph.
// ---------------------------------------------------------------------------
__global__ void head_kernel(const float* __restrict__ pool,
                            const int* __restrict__ batch,
                            const float* __restrict__ Wout,
                            const float* __restrict__ bout,
                            float* __restrict__ out) {
    int g = threadIdx.x;
    if (g >= N_GRAPHS) return;

    // lower_bound(batch, g)
    int lo = 0, hi = N_NODES;
    while (lo < hi) { int m = (lo + hi) >> 1; if (batch[m] < g) lo = m + 1; else hi = m; }
    int s0 = lo;
    // lower_bound(batch, g+1)
    lo = 0; hi = N_NODES;
    while (lo < hi) { int m = (lo + hi) >> 1; if (batch[m] < g + 1) lo = m + 1; else hi = m; }
    int cnt = lo - s0;

    float inv = 1.0f / fmaxf((float)cnt, 1.0f);

    float logits[OUT_DIM];
    float mx = -3.0e38f;
#pragma unroll
    for (int j = 0; j < OUT_DIM; j++) {
        float s = bout[j];
        for (int k = 0; k < HID; k++)
            s += pool[g * HID + k] * inv * Wout[j * HID + k];
        logits[j] = s;
        mx = fmaxf(mx, s);
    }
    float sum = 0.0f;
#pragma unroll
    for (int j = 0; j < OUT_DIM; j++) {
        float e = expf(logits[j] - mx);
        logits[j] = e;
        sum += e;
    }
    float isum = 1.0f / sum;
#pragma unroll
    for (int j = 0; j < OUT_DIM; j++)
        out[g * OUT_DIM + j] = logits[j] * isum;
}

// ---------------------------------------------------------------------------
extern "C" void kernel_launch(void* const* d_in, const int* in_sizes, int n_in,
                              void* d_out, int out_size) {
    const float* X    = (const float*)d_in[0];
    const float* vals = (const float*)d_in[1];
    const float* W1   = (const float*)d_in[2];
    const float* b1   = (const float*)d_in[3];
    const float* W2   = (const float*)d_in[4];
    const float* b2   = (const float*)d_in[5];
    const float* W3   = (const float*)d_in[6];
    const float* b3   = (const float*)d_in[7];
    const float* Wout = (const float*)d_in[8];
    const float* bout = (const float*)d_in[9];
    const int* rows   = (const int*)d_in[10];
    const int* cols   = (const int*)d_in[11];
    const int* batch  = (const int*)d_in[12];
    float* out = (float*)d_out;

    void *pT, *p1, *p2, *p3, *pp;
    cudaGetSymbolAddress(&pT, g_T);
    cudaGetSymbolAddress(&p1, g_X1);
    cudaGetSymbolAddress(&p2, g_X2);
    cudaGetSymbolAddress(&p3, g_X3);
    cudaGetSymbolAddress(&pp, g_pool);

    const size_t bytesH = (size_t)N_NODES * HID * sizeof(float);
    cudaMemsetAsync(p1, 0, bytesH);
    cudaMemsetAsync(p2, 0, bytesH);
    cudaMemsetAsync(p3, 0, bytesH);
    cudaMemsetAsync(pp, 0, (size_t)N_GRAPHS * HID * sizeof(float));

    const int gemm_grid = (N_NODES + 63) / 64;          // 1563
    const int spmm_grid = (N_EDGES * 4) / 256;          // 50000 (exact)
    const int relu_grid = (N_NODES * HID / 4 + 255) / 256;
    const int pool_grid = (N_NODES * 16 + 255) / 256;

    // Layer 1
    linear_kernel<IN_DIM><<<gemm_grid, 256>>>(X, W1, b1, (float*)pT);
    spmm_kernel<<<spmm_grid, 256>>>(rows, cols, vals, (float*)pT, (float*)p1);
    relu_kernel<<<relu_grid, 256>>>((float*)p1);
    // Layer 2
    linear_kernel<HID><<<gemm_grid, 256>>>((float*)p1, W2, b2, (float*)pT);
    spmm_kernel<<<spmm_grid, 256>>>(rows, cols, vals, (float*)pT, (float*)p2);
    relu_kernel<<<relu_grid, 256>>>((float*)p2);
    // Layer 3
    linear_kernel<HID><<<gemm_grid, 256>>>((float*)p2, W3, b3, (float*)pT);
    spmm_kernel<<<spmm_grid, 256>>>(rows, cols, vals, (float*)pT, (float*)p3);
    relu_kernel<<<relu_grid, 256>>>((float*)p3);
    // Pool + head
    pool_kernel<<<pool_grid, 256>>>((float*)p1, (float*)p2, (float*)p3, batch, (float*)pp);
    head_kernel<<<1, 64>>>((float*)pp, batch, Wout, bout, out);
}

// round 6
// speedup vs baseline: 2.8901x; 2.8901x over previous
#include <cuda_runtime.h>

#define N_NODES 100000
#define N_EDGES 3200000
#define IN_DIM  128
#define HID     64
#define N_GRAPHS 64
#define OUT_DIM 10

#define SCAN_BLK 1024
#define N_SCAN_BLOCKS ((N_NODES + SCAN_BLK - 1) / SCAN_BLK)   // 98

// Device-global scratch (no dynamic allocation allowed)
__device__ int   g_off[N_NODES + 1];      // counts -> row offsets
__device__ int   g_pos[N_NODES];          // scatter cursors
__device__ int   g_psum[128];             // scan block sums
__device__ int2  g_edge[N_EDGES];         // CSR payload: (col, val-bits)
__device__ float g_T [(size_t)N_NODES * HID];   // linear output (pre-SpMM)
__device__ float g_X1[(size_t)N_NODES * HID];
__device__ float g_X2[(size_t)N_NODES * HID];
__device__ float g_X3[(size_t)N_NODES * HID];
__device__ float g_pool[N_GRAPHS * HID];  // pooled means (final)

// ---------------------------------------------------------------------------
// Dense linear: out[i,h] = bias[h] + sum_k in[i,k] * W[h,k]
// ---------------------------------------------------------------------------
template<int K>
__global__ void linear_kernel(const float* __restrict__ in,
                              const float* __restrict__ W,
                              const float* __restrict__ bias,
                              float* __restrict__ out) {
    __shared__ __align__(16) float As[16][68];
    __shared__ __align__(16) float Bs[16][68];

    const int tid = threadIdx.x;          // 0..255
    const int tx  = tid & 15;             // col group
    const int ty  = tid >> 4;             // row group
    const int i0  = blockIdx.x * 64;

    float bj[4];
#pragma unroll
    for (int j = 0; j < 4; j++) bj[j] = bias[(tx << 2) + j];

    float acc[4][4];
#pragma unroll
    for (int i = 0; i < 4; i++)
#pragma unroll
        for (int j = 0; j < 4; j++) acc[i][j] = bj[j];

    const int lm = tid >> 2;              // 0..63
    const int lk = (tid & 3) << 2;        // 0,4,8,12
    int grow = i0 + lm;
    if (grow >= N_NODES) grow = N_NODES - 1;

    const float* inp = in + (size_t)grow * K;
    const float* wp  = W  + (size_t)lm * K;

    for (int k0 = 0; k0 < K; k0 += 16) {
        float4 a = *(const float4*)(inp + k0 + lk);
        float4 w = *(const float4*)(wp  + k0 + lk);
        As[lk + 0][lm] = a.x; As[lk + 1][lm] = a.y;
        As[lk + 2][lm] = a.z; As[lk + 3][lm] = a.w;
        Bs[lk + 0][lm] = w.x; Bs[lk + 1][lm] = w.y;
        Bs[lk + 2][lm] = w.z; Bs[lk + 3][lm] = w.w;
        __syncthreads();
#pragma unroll
        for (int kk = 0; kk < 16; kk++) {
            float4 av = *(const float4*)(&As[kk][ty << 2]);
            float4 bv = *(const float4*)(&Bs[kk][tx << 2]);
            acc[0][0] += av.x * bv.x; acc[0][1] += av.x * bv.y;
            acc[0][2] += av.x * bv.z; acc[0][3] += av.x * bv.w;
            acc[1][0] += av.y * bv.x; acc[1][1] += av.y * bv.y;
            acc[1][2] += av.y * bv.z; acc[1][3] += av.y * bv.w;
            acc[2][0] += av.z * bv.x; acc[2][1] += av.z * bv.y;
            acc[2][2] += av.z * bv.z; acc[2][3] += av.z * bv.w;
            acc[3][0] += av.w * bv.x; acc[3][1] += av.w * bv.y;
            acc[3][2] += av.w * bv.z; acc[3][3] += av.w * bv.w;
        }
        __syncthreads();
    }

#pragma unroll
    for (int i = 0; i < 4; i++) {
        int r = i0 + (ty << 2) + i;
        if (r < N_NODES) {
            float4 v = make_float4(acc[i][0], acc[i][1], acc[i][2], acc[i][3]);
            *(float4*)(out + (size_t)r * HID + (tx << 2)) = v;
        }
    }
}

// ---------------------------------------------------------------------------
// CSR build step 1: histogram of row indices
// ---------------------------------------------------------------------------
__global__ void hist_kernel(const int* __restrict__ rows, int* __restrict__ cnt) {
    int e = blockIdx.x * blockDim.x + threadIdx.x;
    if (e < N_EDGES) atomicAdd(&cnt[rows[e]], 1);
}

// CSR build step 2a: per-block exclusive scan (in place), emit block sums
__global__ void scan_block_kernel(int* __restrict__ data, int* __restrict__ bsums) {
    __shared__ int sh[SCAN_BLK];
    int i = blockIdx.x * SCAN_BLK + threadIdx.x;
    int v = (i < N_NODES) ? data[i] : 0;
    sh[threadIdx.x] = v;
    __syncthreads();
    for (int d = 1; d < SCAN_BLK; d <<= 1) {
        int t = (threadIdx.x >= d) ? sh[threadIdx.x - d] : 0;
        __syncthreads();
        sh[threadIdx.x] += t;
        __syncthreads();
    }
    if (i < N_NODES) data[i] = sh[threadIdx.x] - v;   // exclusive
    if (threadIdx.x == SCAN_BLK - 1) bsums[blockIdx.x] = sh[SCAN_BLK - 1];
}

// CSR build step 2b: exclusive scan of the block sums (single block)
__global__ void scan_top_kernel(int* __restrict__ bsums) {
    __shared__ int sh[128];
    int v = (threadIdx.x < N_SCAN_BLOCKS) ? bsums[threadIdx.x] : 0;
    sh[threadIdx.x] = v;
    __syncthreads();
    for (int d = 1; d < 128; d <<= 1) {
        int t = (threadIdx.x >= d) ? sh[threadIdx.x - d] : 0;
        __syncthreads();
        sh[threadIdx.x] += t;
        __syncthreads();
    }
    if (threadIdx.x < N_SCAN_BLOCKS) bsums[threadIdx.x] = sh[threadIdx.x] - v;
}

// CSR build step 2c: add block offsets, init scatter cursors, seal tail
__global__ void add_off_kernel(int* __restrict__ data, const int* __restrict__ bsums,
                               int* __restrict__ pos) {
    int i = blockIdx.x * blockDim.x + threadIdx.x;
    if (i < N_NODES) {
        int o = data[i] + bsums[i >> 10];
        data[i] = o;
        pos[i] = o;
    }
    if (i == 0) data[N_NODES] = N_EDGES;
}

// CSR build step 3: scatter edges into CSR order
__global__ void scatter_kernel(const int* __restrict__ rows,
                               const int* __restrict__ cols,
                               const float* __restrict__ vals,
                               int* __restrict__ pos, int2* __restrict__ edge) {
    int e = blockIdx.x * blockDim.x + threadIdx.x;
    if (e >= N_EDGES) return;
    int p = atomicAdd(&pos[rows[e]], 1);
    edge[p] = make_int2(cols[e], __float_as_int(vals[e]));
}

// ---------------------------------------------------------------------------
// CSR SpMM with fused ReLU: out[r,:] = relu(sum_e val * H[col,:])
// One warp per row; lane owns a float2 slice (64 floats / 32 lanes).
// ---------------------------------------------------------------------------
__global__ void spmm_csr_kernel(const int* __restrict__ off,
                                const int2* __restrict__ edge,
                                const float* __restrict__ H,
                                float* __restrict__ out) {
    const int lane = threadIdx.x & 31;
    const int r = blockIdx.x * (blockDim.x >> 5) + (threadIdx.x >> 5);
    if (r >= N_NODES) return;

    const int s = off[r];
    const int e = off[r + 1];
    float2 acc = make_float2(0.0f, 0.0f);

    for (int base = s; base < e; base += 32) {
        int idx = base + lane;
        int2 ev = (idx < e) ? edge[idx] : make_int2(0, 0);
        int n = e - base;
        if (n >= 32) {
#pragma unroll 8
            for (int j = 0; j < 32; j++) {
                int   c = __shfl_sync(0xffffffffu, ev.x, j);
                float v = __int_as_float(__shfl_sync(0xffffffffu, ev.y, j));
                float2 h = *((const float2*)(H + (size_t)c * HID) + lane);
                acc.x += v * h.x;
                acc.y += v * h.y;
            }
        } else {
            for (int j = 0; j < n; j++) {
                int   c = __shfl_sync(0xffffffffu, ev.x, j);
                float v = __int_as_float(__shfl_sync(0xffffffffu, ev.y, j));
                float2 h = *((const float2*)(H + (size_t)c * HID) + lane);
                acc.x += v * h.x;
                acc.y += v * h.y;
            }
        }
    }

    acc.x = fmaxf(acc.x, 0.0f);
    acc.y = fmaxf(acc.y, 0.0f);
    *((float2*)(out + (size_t)r * HID) + lane) = acc;
}

// ---------------------------------------------------------------------------
// Global mean pool: one block per graph (batch sorted -> contiguous segment).
// Writes pooled mean (already /3 and /count). No atomics.
// ---------------------------------------------------------------------------
__global__ void pool_kernel(const float* __restrict__ X1,
                            const float* __restrict__ X2,
                            const float* __restrict__ X3,
                            const int* __restrict__ batch,
                            float* __restrict__ pool) {
    const int g = blockIdx.x;
    __shared__ int bnd[2];
    if (threadIdx.x < 2) {
        int target = g + threadIdx.x;
        int lo = 0, hi = N_NODES;
        while (lo < hi) { int m = (lo + hi) >> 1; if (batch[m] < target) lo = m + 1; else hi = m; }
        bnd[threadIdx.x] = lo;
    }
    __syncthreads();
    const int s0 = bnd[0], s1 = bnd[1];
    const int lane = threadIdx.x & 31;
    const int w = threadIdx.x >> 5;          // 8 warps

    float2 acc = make_float2(0.0f, 0.0f);
    for (int i = s0 + w; i < s1; i += 8) {
        size_t o = (size_t)i * HID;
        float2 a = *((const float2*)(X1 + o) + lane);
        float2 b = *((const float2*)(X2 + o) + lane);
        float2 c = *((const float2*)(X3 + o) + lane);
        acc.x += a.x + b.x + c.x;
        acc.y += a.y + b.y + c.y;
    }

    __shared__ float2 sh[8][32];
    sh[w][lane] = acc;
    __syncthreads();
    if (w == 0) {
        float2 t = sh[0][lane];
#pragma unroll
        for (int k = 1; k < 8; k++) { t.x += sh[k][lane].x; t.y += sh[k][lane].y; }
        float cnt = fmaxf((float)(s1 - s0), 1.0f);
        float sc = 1.0f / (3.0f * cnt);
        *((float2*)(pool + (size_t)g * HID) + lane) = make_float2(t.x * sc, t.y * sc);
    }
}

// ---------------------------------------------------------------------------
// Head: linear + softmax on pooled means. One thread per graph.
// ---------------------------------------------------------------------------
__global__ void head_kernel(const float* __restrict__ pool,
                            const float* __restrict__ Wout,
                            const float* __restrict__ bout,
                            float* __restrict__ out) {
    int g = threadIdx.x;
    if (g >= N_GRAPHS) return;

    float logits[OUT_DIM];
    float mx = -3.0e38f;
#pragma unroll
    for (int j = 0; j < OUT_DIM; j++) {
        float s = bout[j];
        for (int k = 0; k < HID; k++)
            s += pool[g * HID + k] * Wout[j * HID + k];
        logits[j] = s;
        mx = fmaxf(mx, s);
    }
    float sum = 0.0f;
#pragma unroll
    for (int j = 0; j < OUT_DIM; j++) {
        float e = expf(logits[j] - mx);
        logits[j] = e;
        sum += e;
    }
    float isum = 1.0f / sum;
#pragma unroll
    for (int j = 0; j < OUT_DIM; j++)
        out[g * OUT_DIM + j] = logits[j] * isum;
}

// ---------------------------------------------------------------------------
extern "C" void kernel_launch(void* const* d_in, const int* in_sizes, int n_in,
                              void* d_out, int out_size) {
    const float* X    = (const float*)d_in[0];
    const float* vals = (const float*)d_in[1];
    const float* W1   = (const float*)d_in[2];
    const float* b1   = (const float*)d_in[3];
    const float* W2   = (const float*)d_in[4];
    const float* b2   = (const float*)d_in[5];
    const float* W3   = (const float*)d_in[6];
    const float* b3   = (const float*)d_in[7];
    const float* Wout = (const float*)d_in[8];
    const float* bout = (const float*)d_in[9];
    const int* rows   = (const int*)d_in[10];
    const int* cols   = (const int*)d_in[11];
    const int* batch  = (const int*)d_in[12];
    float* out = (float*)d_out;

    void *pOff, *pPos, *pPsum, *pEdge, *pT, *p1, *p2, *p3, *pp;
    cudaGetSymbolAddress(&pOff,  g_off);
    cudaGetSymbolAddress(&pPos,  g_pos);
    cudaGetSymbolAddress(&pPsum, g_psum);
    cudaGetSymbolAddress(&pEdge, g_edge);
    cudaGetSymbolAddress(&pT, g_T);
    cudaGetSymbolAddress(&p1, g_X1);
    cudaGetSymbolAddress(&p2, g_X2);
    cudaGetSymbolAddress(&p3, g_X3);
    cudaGetSymbolAddress(&pp, g_pool);

    // ---- CSR build (per call; no caching allowed) ----
    cudaMemsetAsync(pOff, 0, (size_t)(N_NODES + 1) * sizeof(int));
    const int egrid = (N_EDGES + 255) / 256;
    hist_kernel<<<egrid, 256>>>(rows, (int*)pOff);
    scan_block_kernel<<<N_SCAN_BLOCKS, SCAN_BLK>>>((int*)pOff, (int*)pPsum);
    scan_top_kernel<<<1, 128>>>((int*)pPsum);
    add_off_kernel<<<(N_NODES + 255) / 256, 256>>>((int*)pOff, (int*)pPsum, (int*)pPos);
    scatter_kernel<<<egrid, 256>>>(rows, cols, vals, (int*)pPos, (int2*)pEdge);

    const int gemm_grid = (N_NODES + 63) / 64;        // 1563
    const int spmm_grid = N_NODES / 8;                // 12500 (exact: 8 warps/block)

    // Layer 1
    linear_kernel<IN_DIM><<<gemm_grid, 256>>>(X, W1, b1, (float*)pT);
    spmm_csr_kernel<<<spmm_grid, 256>>>((int*)pOff, (const int2*)pEdge, (float*)pT, (float*)p1);
    // Layer 2
    linear_kernel<HID><<<gemm_grid, 256>>>((float*)p1, W2, b2, (float*)pT);
    spmm_csr_kernel<<<spmm_grid, 256>>>((int*)pOff, (const int2*)pEdge, (float*)pT, (float*)p2);
    // Layer 3
    linear_kernel<HID><<<gemm_grid, 256>>>((float*)p2, W3, b3, (float*)pT);
    spmm_csr_kernel<<<spmm_grid, 256>>>((int*)pOff, (const int2*)pEdge, (float*)pT, (float*)p3);
    // Pool + head
    pool_kernel<<<N_GRAPHS, 256>>>((float*)p1, (float*)p2, (float*)p3, batch, (float*)pp);
    head_kernel<<<1, 64>>>((float*)pp, Wout, bout, out);
}

// round 9
// speedup vs baseline: 3.0074x; 1.0406x over previous
#include <cuda_runtime.h>
#include <cuda_fp16.h>

#define N_NODES 100000
#define N_EDGES 3200000
#define IN_DIM  128
#define HID     64
#define N_GRAPHS 64
#define OUT_DIM 10

#define SCAN_BLK 1024
#define N_SCAN_BLOCKS ((N_NODES + SCAN_BLK - 1) / SCAN_BLK)   // 98

// Device-global scratch (no dynamic allocation allowed)
__device__ int    g_off[N_NODES + 1];
__device__ int    g_pos[N_NODES];
__device__ int    g_psum[128];
__device__ int2   g_edge[N_EDGES];
__device__ __half g_T [(size_t)N_NODES * HID];   // linear output (fp16, pre-SpMM)
__device__ float  g_X1[(size_t)N_NODES * HID];
__device__ float  g_X2[(size_t)N_NODES * HID];
__device__ float  g_X3[(size_t)N_NODES * HID];
__device__ float  g_pool[N_GRAPHS * HID];

// ---------------------------------------------------------------------------
// Dense linear: out[i,h] = bias[h] + sum_k in[i,k] * W[h,k], output fp16
// ---------------------------------------------------------------------------
template<int K>
__global__ void linear_kernel(const float* __restrict__ in,
                              const float* __restrict__ W,
                              const float* __restrict__ bias,
                              __half* __restrict__ out) {
    __shared__ __align__(16) float As[16][68];
    __shared__ __align__(16) float Bs[16][68];

    const int tid = threadIdx.x;          // 0..255
    const int tx  = tid & 15;             // col group
    const int ty  = tid >> 4;             // row group
    const int i0  = blockIdx.x * 64;

    float bj[4];
#pragma unroll
    for (int j = 0; j < 4; j++) bj[j] = bias[(tx << 2) + j];

    float acc[4][4];
#pragma unroll
    for (int i = 0; i < 4; i++)
#pragma unroll
        for (int j = 0; j < 4; j++) acc[i][j] = bj[j];

    const int lm = tid >> 2;              // 0..63
    const int lk = (tid & 3) << 2;        // 0,4,8,12
    int grow = i0 + lm;
    if (grow >= N_NODES) grow = N_NODES - 1;

    const float* inp = in + (size_t)grow * K;
    const float* wp  = W  + (size_t)lm * K;

    for (int k0 = 0; k0 < K; k0 += 16) {
        float4 a = *(const float4*)(inp + k0 + lk);
        float4 w = *(const float4*)(wp  + k0 + lk);
        As[lk + 0][lm] = a.x; As[lk + 1][lm] = a.y;
        As[lk + 2][lm] = a.z; As[lk + 3][lm] = a.w;
        Bs[lk + 0][lm] = w.x; Bs[lk + 1][lm] = w.y;
        Bs[lk + 2][lm] = w.z; Bs[lk + 3][lm] = w.w;
        __syncthreads();
#pragma unroll
        for (int kk = 0; kk < 16; kk++) {
            float4 av = *(const float4*)(&As[kk][ty << 2]);
            float4 bv = *(const float4*)(&Bs[kk][tx << 2]);
            acc[0][0] += av.x * bv.x; acc[0][1] += av.x * bv.y;
            acc[0][2] += av.x * bv.z; acc[0][3] += av.x * bv.w;
            acc[1][0] += av.y * bv.x; acc[1][1] += av.y * bv.y;
            acc[1][2] += av.y * bv.z; acc[1][3] += av.y * bv.w;
            acc[2][0] += av.z * bv.x; acc[2][1] += av.z * bv.y;
            acc[2][2] += av.z * bv.z; acc[2][3] += av.z * bv.w;
            acc[3][0] += av.w * bv.x; acc[3][1] += av.w * bv.y;
            acc[3][2] += av.w * bv.z; acc[3][3] += av.w * bv.w;
        }
        __syncthreads();
    }

#pragma unroll
    for (int i = 0; i < 4; i++) {
        int r = i0 + (ty << 2) + i;
        if (r < N_NODES) {
            __half2* op = (__half2*)(out + (size_t)r * HID) + (tx << 1);
            op[0] = __floats2half2_rn(acc[i][0], acc[i][1]);
            op[1] = __floats2half2_rn(acc[i][2], acc[i][3]);
        }
    }
}

// ---------------------------------------------------------------------------
// CSR build step 1: histogram of row indices (4 edges/thread)
// ---------------------------------------------------------------------------
__global__ void hist_kernel(const int4* __restrict__ rows4, int* __restrict__ cnt) {
    int i = blockIdx.x * blockDim.x + threadIdx.x;
    if (i < N_EDGES / 4) {
        int4 r = rows4[i];
        atomicAdd(&cnt[r.x], 1);
        atomicAdd(&cnt[r.y], 1);
        atomicAdd(&cnt[r.z], 1);
        atomicAdd(&cnt[r.w], 1);
    }
}

// CSR build step 2a: per-block exclusive scan (in place), emit block sums
__global__ void scan_block_kernel(int* __restrict__ data, int* __restrict__ bsums) {
    __shared__ int sh[SCAN_BLK];
    int i = blockIdx.x * SCAN_BLK + threadIdx.x;
    int v = (i < N_NODES) ? data[i] : 0;
    sh[threadIdx.x] = v;
    __syncthreads();
    for (int d = 1; d < SCAN_BLK; d <<= 1) {
        int t = (threadIdx.x >= d) ? sh[threadIdx.x - d] : 0;
        __syncthreads();
        sh[threadIdx.x] += t;
        __syncthreads();
    }
    if (i < N_NODES) data[i] = sh[threadIdx.x] - v;   // exclusive
    if (threadIdx.x == SCAN_BLK - 1) bsums[blockIdx.x] = sh[SCAN_BLK - 1];
}

// CSR build step 2b: exclusive scan of the block sums (single block)
__global__ void scan_top_kernel(int* __restrict__ bsums) {
    __shared__ int sh[128];
    int v = (threadIdx.x < N_SCAN_BLOCKS) ? bsums[threadIdx.x] : 0;
    sh[threadIdx.x] = v;
    __syncthreads();
    for (int d = 1; d < 128; d <<= 1) {
        int t = (threadIdx.x >= d) ? sh[threadIdx.x - d] : 0;
        __syncthreads();
        sh[threadIdx.x] += t;
        __syncthreads();
    }
    if (threadIdx.x < N_SCAN_BLOCKS) bsums[threadIdx.x] = sh[threadIdx.x] - v;
}

// CSR build step 2c: add block offsets, init scatter cursors, seal tail
__global__ void add_off_kernel(int* __restrict__ data, const int* __restrict__ bsums,
                               int* __restrict__ pos) {
    int i = blockIdx.x * blockDim.x + threadIdx.x;
    if (i < N_NODES) {
        int o = data[i] + bsums[i >> 10];
        data[i] = o;
        pos[i] = o;
    }
    if (i == 0) data[N_NODES] = N_EDGES;
}

// CSR build step 3: scatter edges into CSR order (4 edges/thread)
__global__ void scatter_kernel(const int4* __restrict__ rows4,
                               const int4* __restrict__ cols4,
                               const float4* __restrict__ vals4,
                               int* __restrict__ pos, int2* __restrict__ edge) {
    int i = blockIdx.x * blockDim.x + threadIdx.x;
    if (i >= N_EDGES / 4) return;
    int4 r = rows4[i];
    int4 c = cols4[i];
    float4 v = vals4[i];
    int p;
    p = atomicAdd(&pos[r.x], 1); edge[p] = make_int2(c.x, __float_as_int(v.x));
    p = atomicAdd(&pos[r.y], 1); edge[p] = make_int2(c.y, __float_as_int(v.y));
    p = atomicAdd(&pos[r.z], 1); edge[p] = make_int2(c.z, __float_as_int(v.z));
    p = atomicAdd(&pos[r.w], 1); edge[p] = make_int2(c.w, __float_as_int(v.w));
}

// ---------------------------------------------------------------------------
// CSR SpMM with fused ReLU: out[r,:] = relu(sum_e val * H[col,:])
// One warp per row; H is fp16 (128B/row, one L2 line per gather);
// lane owns one half2 (2 channels); accumulate in fp32.
// ---------------------------------------------------------------------------
__global__ void spmm_csr_kernel(const int* __restrict__ off,
                                const int2* __restrict__ edge,
                                const __half* __restrict__ H,
                                float* __restrict__ out) {
    const int lane = threadIdx.x & 31;
    const int r = blockIdx.x * (blockDim.x >> 5) + (threadIdx.x >> 5);
    if (r >= N_NODES) return;

    const int s = off[r];
    const int e = off[r + 1];
    float2 acc = make_float2(0.0f, 0.0f);

    for (int base = s; base < e; base += 32) {
        int idx = base + lane;
        int2 ev = (idx < e) ? edge[idx] : make_int2(0, 0);
        int n = e - base;
        if (n >= 32) {
#pragma unroll 8
            for (int j = 0; j < 32; j++) {
                int   c = __shfl_sync(0xffffffffu, ev.x, j);
                float v = __int_as_float(__shfl_sync(0xffffffffu, ev.y, j));
                float2 h = __half22float2(*((const __half2*)(H + (size_t)c * HID) + lane));
                acc.x += v * h.x;
                acc.y += v * h.y;
            }
        } else {
            for (int j = 0; j < n; j++) {
                int   c = __shfl_sync(0xffffffffu, ev.x, j);
                float v = __int_as_float(__shfl_sync(0xffffffffu, ev.y, j));
                float2 h = __half22float2(*((const __half2*)(H + (size_t)c * HID) + lane));
                acc.x += v * h.x;
                acc.y += v * h.y;
            }
        }
    }

    acc.x = fmaxf(acc.x, 0.0f);
    acc.y = fmaxf(acc.y, 0.0f);
    *((float2*)(out + (size_t)r * HID) + lane) = acc;
}

// ---------------------------------------------------------------------------
// Global mean pool: one block per graph (batch sorted -> contiguous segment)
// ---------------------------------------------------------------------------
__global__ void pool_kernel(const float* __restrict__ X1,
                            const float* __restrict__ X2,
                            const float* __restrict__ X3,
                            const int* __restrict__ batch,
                            float* __restrict__ pool) {
    const int g = blockIdx.x;
    __shared__ int bnd[2];
    if (threadIdx.x < 2) {
        int target = g + threadIdx.x;
        int lo = 0, hi = N_NODES;
        while (lo < hi) { int m = (lo + hi) >> 1; if (batch[m] < target) lo = m + 1; else hi = m; }
        bnd[threadIdx.x] = lo;
    }
    __syncthreads();
    const int s0 = bnd[0], s1 = bnd[1];
    const int lane = threadIdx.x & 31;
    const int w = threadIdx.x >> 5;          // 8 warps

    float2 acc = make_float2(0.0f, 0.0f);
    for (int i = s0 + w; i < s1; i += 8) {
        size_t o = (size_t)i * HID;
        float2 a = *((const float2*)(X1 + o) + lane);
        float2 b = *((const float2*)(X2 + o) + lane);
        float2 c = *((const float2*)(X3 + o) + lane);
        acc.x += a.x + b.x + c.x;
        acc.y += a.y + b.y + c.y;
    }

    __shared__ float2 sh[8][32];
    sh[w][lane] = acc;
    __syncthreads();
    if (w == 0) {
        float2 t = sh[0][lane];
#pragma unroll
        for (int k = 1; k < 8; k++) { t.x += sh[k][lane].x; t.y += sh[k][lane].y; }
        float cnt = fmaxf((float)(s1 - s0), 1.0f);
        float sc = 1.0f / (3.0f * cnt);
        *((float2*)(pool + (size_t)g * HID) + lane) = make_float2(t.x * sc, t.y * sc);
    }
}

// ---------------------------------------------------------------------------
// Head: linear + softmax on pooled means. One thread per graph.
// ---------------------------------------------------------------------------
__global__ void head_kernel(const float* __restrict__ pool,
                            const float* __restrict__ Wout,
                            const float* __restrict__ bout,
                            float* __restrict__ out) {
    int g = threadIdx.x;
    if (g >= N_GRAPHS) return;

    float logits[OUT_DIM];
    float mx = -3.0e38f;
#pragma unroll
    for (int j = 0; j < OUT_DIM; j++) {
        float s = bout[j];
        for (int k = 0; k < HID; k++)
            s += pool[g * HID + k] * Wout[j * HID + k];
        logits[j] = s;
        mx = fmaxf(mx, s);
    }
    float sum = 0.0f;
#pragma unroll
    for (int j = 0; j < OUT_DIM; j++) {
        float e = expf(logits[j] - mx);
        logits[j] = e;
        sum += e;
    }
    float isum = 1.0f / sum;
#pragma unroll
    for (int j = 0; j < OUT_DIM; j++)
        out[g * OUT_DIM + j] = logits[j] * isum;
}

// ---------------------------------------------------------------------------
extern "C" void kernel_launch(void* const* d_in, const int* in_sizes, int n_in,
                              void* d_out, int out_size) {
    const float* X    = (const float*)d_in[0];
    const float* vals = (const float*)d_in[1];
    const float* W1   = (const float*)d_in[2];
    const float* b1   = (const float*)d_in[3];
    const float* W2   = (const float*)d_in[4];
    const float* b2   = (const float*)d_in[5];
    const float* W3   = (const float*)d_in[6];
    const float* b3   = (const float*)d_in[7];
    const float* Wout = (const float*)d_in[8];
    const float* bout = (const float*)d_in[9];
    const int* rows   = (const int*)d_in[10];
    const int* cols   = (const int*)d_in[11];
    const int* batch  = (const int*)d_in[12];
    float* out = (float*)d_out;

    void *pOff, *pPos, *pPsum, *pEdge, *pT, *p1, *p2, *p3, *pp;
    cudaGetSymbolAddress(&pOff,  g_off);
    cudaGetSymbolAddress(&pPos,  g_pos);
    cudaGetSymbolAddress(&pPsum, g_psum);
    cudaGetSymbolAddress(&pEdge, g_edge);
    cudaGetSymbolAddress(&pT, g_T);
    cudaGetSymbolAddress(&p1, g_X1);
    cudaGetSymbolAddress(&p2, g_X2);
    cudaGetSymbolAddress(&p3, g_X3);
    cudaGetSymbolAddress(&pp, g_pool);

    // ---- CSR build ----
    cudaMemsetAsync(pOff, 0, (size_t)(N_NODES + 1) * sizeof(int));
    const int e4grid = (N_EDGES / 4 + 255) / 256;   // 3125
    hist_kernel<<<e4grid, 256>>>((const int4*)rows, (int*)pOff);
    scan_block_kernel<<<N_SCAN_BLOCKS, SCAN_BLK>>>((int*)pOff, (int*)pPsum);
    scan_top_kernel<<<1, 128>>>((int*)pPsum);
    add_off_kernel<<<(N_NODES + 255) / 256, 256>>>((int*)pOff, (int*)pPsum, (int*)pPos);
    scatter_kernel<<<e4grid, 256>>>((const int4*)rows, (const int4*)cols,
                                    (const float4*)vals, (int*)pPos, (int2*)pEdge);

    const int gemm_grid = (N_NODES + 63) / 64;        // 1563
    const int spmm_grid = N_NODES / 8;                // 12500 (8 warps/block)

    // Layer 1
    linear_kernel<IN_DIM><<<gemm_grid, 256>>>(X, W1, b1, (__half*)pT);
    spmm_csr_kernel<<<spmm_grid, 256>>>((int*)pOff, (const int2*)pEdge, (const __half*)pT, (float*)p1);
    // Layer 2
    linear_kernel<HID><<<gemm_grid, 256>>>((float*)p1, W2, b2, (__half*)pT);
    spmm_csr_kernel<<<spmm_grid, 256>>>((int*)pOff, (const int2*)pEdge, (const __half*)pT, (float*)p2);
    // Layer 3
    linear_kernel<HID><<<gemm_grid, 256>>>((float*)p2, W3, b3, (__half*)pT);
    spmm_csr_kernel<<<spmm_grid, 256>>>((int*)pOff, (const int2*)pEdge, (const __half*)pT, (float*)p3);
    // Pool + head
    pool_kernel<<<N_GRAPHS, 256>>>((float*)p1, (float*)p2, (float*)p3, batch, (float*)pp);
    head_kernel<<<1, 64>>>((float*)pp, Wout, bout, out);
}

// round 11
// speedup vs baseline: 3.1560x; 1.0494x over previous
#include <cuda_runtime.h>
#include <cuda_fp16.h>
#include <mma.h>

using namespace nvcuda;

#define N_NODES 100000
#define NPAD    100032          // 64 * 1563, padded row count for wmma tiles
#define N_EDGES 3200000
#define IN_DIM  128
#define HID     64
#define N_GRAPHS 64
#define OUT_DIM 10

#define SCAN_BLK 1024
#define N_SCAN_BLOCKS ((N_NODES + SCAN_BLK - 1) / SCAN_BLK)   // 98

// Device-global scratch (no dynamic allocation allowed)
__device__ int    g_off[N_NODES + 1];
__device__ int    g_pos[N_NODES];
__device__ int    g_psum[128];
__device__ int2   g_edge[N_EDGES];
__device__ __half g_Xh [(size_t)NPAD * IN_DIM];   // fp16 copy of X
__device__ __half g_W1h[HID * IN_DIM];
__device__ __half g_W2h[HID * HID];
__device__ __half g_W3h[HID * HID];
__device__ __half g_T  [(size_t)N_NODES * HID];   // linear output (pre-SpMM)
__device__ __half g_X1h[(size_t)NPAD * HID];
__device__ __half g_X2h[(size_t)NPAD * HID];
__device__ __half g_X3h[(size_t)NPAD * HID];
__device__ float  g_pool[N_GRAPHS * HID];

// ---------------------------------------------------------------------------
// Convert X (fp32) -> g_Xh (fp16), zero pad rows. 4 elems/thread.
// ---------------------------------------------------------------------------
__global__ void convert_x_kernel(const float4* __restrict__ X4, uint2* __restrict__ out) {
    int i = blockIdx.x * blockDim.x + threadIdx.x;
    if (i >= NPAD * IN_DIM / 4) return;
    int row = i >> 5;                       // 32 float4 per 128-wide row
    float4 v = (row < N_NODES) ? X4[i] : make_float4(0.f, 0.f, 0.f, 0.f);
    __half2 h0 = __floats2half2_rn(v.x, v.y);
    __half2 h1 = __floats2half2_rn(v.z, v.w);
    out[i] = make_uint2(*(unsigned*)&h0, *(unsigned*)&h1);
}

// Convert the three weight matrices to fp16 (tiny)
__global__ void convert_w_kernel(const float* __restrict__ W1,
                                 const float* __restrict__ W2,
                                 const float* __restrict__ W3,
                                 __half* __restrict__ o1,
                                 __half* __restrict__ o2,
                                 __half* __restrict__ o3) {
    int i = blockIdx.x * blockDim.x + threadIdx.x;
    if (i < HID * IN_DIM) o1[i] = __float2half(W1[i]);
    if (i < HID * HID) {
        o2[i] = __float2half(W2[i]);
        o3[i] = __float2half(W3[i]);
    }
}

// ---------------------------------------------------------------------------
// Tensor-core linear: out[i,h] = (half)(bias[h] + sum_k A[i,k] * W[h,k])
// A: [NPAD, K] fp16 row-major.  W: [64, K] fp16 row-major (B = W^T via col_major).
// Block: 64 rows x 64 cols, 8 warps, each warp 1 row-tile x 2 col-tiles.
// fp32 accumulate; epilogue through padded smem adds bias, converts to fp16.
// ---------------------------------------------------------------------------
#define CS_LD 72   // 64 + 8 pad; 72*4B = 288B, multiple of 16B (wmma ldm req)

template<int K>
__global__ void linear_wmma_kernel(const __half* __restrict__ A,
                                   const __half* __restrict__ Wh,
                                   const float* __restrict__ bias,
                                   __half* __restrict__ out) {
    __shared__ float Cs[64 * CS_LD];

    const int w    = threadIdx.x >> 5;        // 0..7
    const int r0   = blockIdx.x * 64;
    const int trow = (w >> 1) << 4;           // 0,16,32,48
    const int tcol = (w & 1) << 5;            // 0,32

    wmma::fragment<wmma::accumulator, 16, 16, 16, float> c0, c1;
    wmma::fill_fragment(c0, 0.0f);
    wmma::fill_fragment(c1, 0.0f);
    wmma::fragment<wmma::matrix_a, 16, 16, 16, __half, wmma::row_major> a;
    wmma::fragment<wmma::matrix_b, 16, 16, 16, __half, wmma::col_major> b0, b1;

    const __half* Ap = A + (size_t)(r0 + trow) * K;
#pragma unroll
    for (int k = 0; k < K; k += 16) {
        wmma::load_matrix_sync(a, Ap + k, K);
        wmma::load_matrix_sync(b0, Wh + (size_t)tcol * K + k, K);
        wmma::load_matrix_sync(b1, Wh + (size_t)(tcol + 16) * K + k, K);
        wmma::mma_sync(c0, a, b0, c0);
        wmma::mma_sync(c1, a, b1, c1);
    }
    wmma::store_matrix_sync(&Cs[trow * CS_LD + tcol],      c0, CS_LD, wmma::mem_row_major);
    wmma::store_matrix_sync(&Cs[trow * CS_LD + tcol + 16], c1, CS_LD, wmma::mem_row_major);
    __syncthreads();

    // Epilogue: each thread handles 16 output elems (quarter row)
    const int lr = threadIdx.x >> 2;          // 0..63
    const int cc = (threadIdx.x & 3) << 4;    // 0,16,32,48
    const int r  = r0 + lr;
    if (r < N_NODES) {
        const float* cp = &Cs[lr * CS_LD + cc];
        __half2 h[8];
#pragma unroll
        for (int j = 0; j < 8; j++) {
            float x = cp[2 * j]     + bias[cc + 2 * j];
            float y = cp[2 * j + 1] + bias[cc + 2 * j + 1];
            h[j] = __floats2half2_rn(x, y);
        }
        uint4* op = (uint4*)(out + (size_t)r * HID + cc);
        op[0] = make_uint4(*(unsigned*)&h[0], *(unsigned*)&h[1],
                           *(unsigned*)&h[2], *(unsigned*)&h[3]);
        op[1] = make_uint4(*(unsigned*)&h[4], *(unsigned*)&h[5],
                           *(unsigned*)&h[6], *(unsigned*)&h[7]);
    }
}

// ---------------------------------------------------------------------------
// CSR build step 1: histogram of row indices (4 edges/thread)
// ---------------------------------------------------------------------------
__global__ void hist_kernel(const int4* __restrict__ rows4, int* __restrict__ cnt) {
    int i = blockIdx.x * blockDim.x + threadIdx.x;
    if (i < N_EDGES / 4) {
        int4 r = rows4[i];
        atomicAdd(&cnt[r.x], 1);
        atomicAdd(&cnt[r.y], 1);
        atomicAdd(&cnt[r.z], 1);
        atomicAdd(&cnt[r.w], 1);
    }
}

// CSR build step 2a: per-block exclusive scan (in place), emit block sums
__global__ void scan_block_kernel(int* __restrict__ data, int* __restrict__ bsums) {
    __shared__ int sh[SCAN_BLK];
    int i = blockIdx.x * SCAN_BLK + threadIdx.x;
    int v = (i < N_NODES) ? data[i] : 0;
    sh[threadIdx.x] = v;
    __syncthreads();
    for (int d = 1; d < SCAN_BLK; d <<= 1) {
        int t = (threadIdx.x >= d) ? sh[threadIdx.x - d] : 0;
        __syncthreads();
        sh[threadIdx.x] += t;
        __syncthreads();
    }
    if (i < N_NODES) data[i] = sh[threadIdx.x] - v;   // exclusive
    if (threadIdx.x == SCAN_BLK - 1) bsums[blockIdx.x] = sh[SCAN_BLK - 1];
}

// CSR build step 2b: exclusive scan of the block sums (single block)
__global__ void scan_top_kernel(int* __restrict__ bsums) {
    __shared__ int sh[128];
    int v = (threadIdx.x < N_SCAN_BLOCKS) ? bsums[threadIdx.x] : 0;
    sh[threadIdx.x] = v;
    __syncthreads();
    for (int d = 1; d < 128; d <<= 1) {
        int t = (threadIdx.x >= d) ? sh[threadIdx.x - d] : 0;
        __syncthreads();
        sh[threadIdx.x] += t;
        __syncthreads();
    }
    if (threadIdx.x < N_SCAN_BLOCKS) bsums[threadIdx.x] = sh[threadIdx.x] - v;
}

// CSR build step 2c: add block offsets, init scatter cursors, seal tail
__global__ void add_off_kernel(int* __restrict__ data, const int* __restrict__ bsums,
                               int* __restrict__ pos) {
    int i = blockIdx.x * blockDim.x + threadIdx.x;
    if (i < N_NODES) {
        int o = data[i] + bsums[i >> 10];
        data[i] = o;
        pos[i] = o;
    }
    if (i == 0) data[N_NODES] = N_EDGES;
}

// CSR build step 3: scatter edges into CSR order (4 edges/thread)
__global__ void scatter_kernel(const int4* __restrict__ rows4,
                               const int4* __restrict__ cols4,
                               const float4* __restrict__ vals4,
                               int* __restrict__ pos, int2* __restrict__ edge) {
    int i = blockIdx.x * blockDim.x + threadIdx.x;
    if (i >= N_EDGES / 4) return;
    int4 r = rows4[i];
    int4 c = cols4[i];
    float4 v = vals4[i];
    int p;
    p = atomicAdd(&pos[r.x], 1); edge[p] = make_int2(c.x, __float_as_int(v.x));
    p = atomicAdd(&pos[r.y], 1); edge[p] = make_int2(c.y, __float_as_int(v.y));
    p = atomicAdd(&pos[r.z], 1); edge[p] = make_int2(c.z, __float_as_int(v.z));
    p = atomicAdd(&pos[r.w], 1); edge[p] = make_int2(c.w, __float_as_int(v.w));
}

// ---------------------------------------------------------------------------
// CSR SpMM with fused ReLU: out[r,:] = relu(sum_e val * H[col,:])
// One warp per row; H fp16 (128B/row); lane owns one half2; fp32 accumulate;
// fp16 output.
// ---------------------------------------------------------------------------
__global__ void spmm_csr_kernel(const int* __restrict__ off,
                                const int2* __restrict__ edge,
                                const __half* __restrict__ H,
                                __half* __restrict__ out) {
    const int lane = threadIdx.x & 31;
    const int r = blockIdx.x * (blockDim.x >> 5) + (threadIdx.x >> 5);
    if (r >= N_NODES) return;

    const int s = off[r];
    const int e = off[r + 1];
    float2 acc = make_float2(0.0f, 0.0f);

    for (int base = s; base < e; base += 32) {
        int idx = base + lane;
        int2 ev = (idx < e) ? edge[idx] : make_int2(0, 0);
        int n = e - base;
        if (n >= 32) {
#pragma unroll 8
            for (int j = 0; j < 32; j++) {
                int   c = __shfl_sync(0xffffffffu, ev.x, j);
                float v = __int_as_float(__shfl_sync(0xffffffffu, ev.y, j));
                float2 h = __half22float2(*((const __half2*)(H + (size_t)c * HID) + lane));
                acc.x += v * h.x;
                acc.y += v * h.y;
            }
        } else {
            for (int j = 0; j < n; j++) {
                int   c = __shfl_sync(0xffffffffu, ev.x, j);
                float v = __int_as_float(__shfl_sync(0xffffffffu, ev.y, j));
                float2 h = __half22float2(*((const __half2*)(H + (size_t)c * HID) + lane));
                acc.x += v * h.x;
                acc.y += v * h.y;
            }
        }
    }

    acc.x = fmaxf(acc.x, 0.0f);
    acc.y = fmaxf(acc.y, 0.0f);
    ((__half2*)(out + (size_t)r * HID))[lane] = __floats2half2_rn(acc.x, acc.y);
}

// ---------------------------------------------------------------------------
// Global mean pool over fp16 inputs: one block per graph (batch sorted)
// ---------------------------------------------------------------------------
__global__ void pool_kernel(const __half* __restrict__ X1,
                            const __half* __restrict__ X2,
                            const __half* __restrict__ X3,
                            const int* __restrict__ batch,
                            float* __restrict__ pool) {
    const int g = blockIdx.x;
    __shared__ int bnd[2];
    if (threadIdx.x < 2) {
        int target = g + threadIdx.x;
        int lo = 0, hi = N_NODES;
        while (lo < hi) { int m = (lo + hi) >> 1; if (batch[m] < target) lo = m + 1; else hi = m; }
        bnd[threadIdx.x] = lo;
    }
    __syncthreads();
    const int s0 = bnd[0], s1 = bnd[1];
    const int lane = threadIdx.x & 31;
    const int w = threadIdx.x >> 5;          // 8 warps

    float2 acc = make_float2(0.0f, 0.0f);
    for (int i = s0 + w; i < s1; i += 8) {
        size_t o = (size_t)i * HID;
        float2 a = __half22float2(((const __half2*)(X1 + o))[lane]);
        float2 b = __half22float2(((const __half2*)(X2 + o))[lane]);
        float2 c = __half22float2(((const __half2*)(X3 + o))[lane]);
        acc.x += a.x + b.x + c.x;
        acc.y += a.y + b.y + c.y;
    }

    __shared__ float2 sh[8][32];
    sh[w][lane] = acc;
    __syncthreads();
    if (w == 0) {
        float2 t = sh[0][lane];
#pragma unroll
        for (int k = 1; k < 8; k++) { t.x += sh[k][lane].x; t.y += sh[k][lane].y; }
        float cnt = fmaxf((float)(s1 - s0), 1.0f);
        float sc = 1.0f / (3.0f * cnt);
        *((float2*)(pool + (size_t)g * HID) + lane) = make_float2(t.x * sc, t.y * sc);
    }
}

// ---------------------------------------------------------------------------
// Head: linear + softmax on pooled means. One thread per graph.
// ---------------------------------------------------------------------------
__global__ void head_kernel(const float* __restrict__ pool,
                            const float* __restrict__ Wout,
                            const float* __restrict__ bout,
                            float* __restrict__ out) {
    int g = threadIdx.x;
    if (g >= N_GRAPHS) return;

    float logits[OUT_DIM];
    float mx = -3.0e38f;
#pragma unroll
    for (int j = 0; j < OUT_DIM; j++) {
        float s = bout[j];
        for (int k = 0; k < HID; k++)
            s += pool[g * HID + k] * Wout[j * HID + k];
        logits[j] = s;
        mx = fmaxf(mx, s);
    }
    float sum = 0.0f;
#pragma unroll
    for (int j = 0; j < OUT_DIM; j++) {
        float e = expf(logits[j] - mx);
        logits[j] = e;
        sum += e;
    }
    float isum = 1.0f / sum;
#pragma unroll
    for (int j = 0; j < OUT_DIM; j++)
        out[g * OUT_DIM + j] = logits[j] * isum;
}

// ---------------------------------------------------------------------------
extern "C" void kernel_launch(void* const* d_in, const int* in_sizes, int n_in,
                              void* d_out, int out_size) {
    const float* X    = (const float*)d_in[0];
    const float* vals = (const float*)d_in[1];
    const float* W1   = (const float*)d_in[2];
    const float* b1   = (const float*)d_in[3];
    const float* W2   = (const float*)d_in[4];
    const float* b2   = (const float*)d_in[5];
    const float* W3   = (const float*)d_in[6];
    const float* b3   = (const float*)d_in[7];
    const float* Wout = (const float*)d_in[8];
    const float* bout = (const float*)d_in[9];
    const int* rows   = (const int*)d_in[10];
    const int* cols   = (const int*)d_in[11];
    const int* batch  = (const int*)d_in[12];
    float* out = (float*)d_out;

    void *pOff, *pPos, *pPsum, *pEdge, *pXh, *pW1h, *pW2h, *pW3h;
    void *pT, *p1, *p2, *p3, *pp;
    cudaGetSymbolAddress(&pOff,  g_off);
    cudaGetSymbolAddress(&pPos,  g_pos);
    cudaGetSymbolAddress(&pPsum, g_psum);
    cudaGetSymbolAddress(&pEdge, g_edge);
    cudaGetSymbolAddress(&pXh,  g_Xh);
    cudaGetSymbolAddress(&pW1h, g_W1h);
    cudaGetSymbolAddress(&pW2h, g_W2h);
    cudaGetSymbolAddress(&pW3h, g_W3h);
    cudaGetSymbolAddress(&pT, g_T);
    cudaGetSymbolAddress(&p1, g_X1h);
    cudaGetSymbolAddress(&p2, g_X2h);
    cudaGetSymbolAddress(&p3, g_X3h);
    cudaGetSymbolAddress(&pp, g_pool);

    // ---- fp16 conversions ----
    const int cx_grid = (NPAD * IN_DIM / 4 + 255) / 256;
    convert_x_kernel<<<cx_grid, 256>>>((const float4*)X, (uint2*)pXh);
    convert_w_kernel<<<32, 256>>>(W1, W2, W3, (__half*)pW1h, (__half*)pW2h, (__half*)pW3h);

    // ---- CSR build ----
    cudaMemsetAsync(pOff, 0, (size_t)(N_NODES + 1) * sizeof(int));
    const int e4grid = (N_EDGES / 4 + 255) / 256;   // 3125
    hist_kernel<<<e4grid, 256>>>((const int4*)rows, (int*)pOff);
    scan_block_kernel<<<N_SCAN_BLOCKS, SCAN_BLK>>>((int*)pOff, (int*)pPsum);
    scan_top_kernel<<<1, 128>>>((int*)pPsum);
    add_off_kernel<<<(N_NODES + 255) / 256, 256>>>((int*)pOff, (int*)pPsum, (int*)pPos);
    scatter_kernel<<<e4grid, 256>>>((const int4*)rows, (const int4*)cols,
                                    (const float4*)vals, (int*)pPos, (int2*)pEdge);

    const int gemm_grid = NPAD / 64;                  // 1563
    const int spmm_grid = N_NODES / 8;                // 12500 (8 warps/block)

    // Layer 1
    linear_wmma_kernel<IN_DIM><<<gemm_grid, 256>>>((const __half*)pXh, (const __half*)pW1h, b1, (__half*)pT);
    spmm_csr_kernel<<<spmm_grid, 256>>>((int*)pOff, (const int2*)pEdge, (const __half*)pT, (__half*)p1);
    // Layer 2
    linear_wmma_kernel<HID><<<gemm_grid, 256>>>((const __half*)p1, (const __half*)pW2h, b2, (__half*)pT);
    spmm_csr_kernel<<<spmm_grid, 256>>>((int*)pOff, (const int2*)pEdge, (const __half*)pT, (__half*)p2);
    // Layer 3
    linear_wmma_kernel<HID><<<gemm_grid, 256>>>((const __half*)p2, (const __half*)pW3h, b3, (__half*)pT);
    spmm_csr_kernel<<<spmm_grid, 256>>>((int*)pOff, (const int2*)pEdge, (const __half*)pT, (__half*)p3);
    // Pool + head
    pool_kernel<<<N_GRAPHS, 256>>>((const __half*)p1, (const __half*)p2, (const __half*)p3, batch, (float*)pp);
    head_kernel<<<1, 64>>>((float*)pp, Wout, bout, out);
}

// round 14
// speedup vs baseline: 4.0947x; 1.2974x over previous
#include <cuda_runtime.h>
#include <cuda_fp16.h>
#include <mma.h>

using namespace nvcuda;

#define N_NODES 100000
#define NPAD    100032          // 64 * 1563, padded row count for wmma tiles
#define N_EDGES 3200000
#define IN_DIM  128
#define HID     64
#define N_GRAPHS 64
#define OUT_DIM 10

#define SCAN_BLK 1024
#define N_SCAN_BLOCKS ((N_NODES + SCAN_BLK - 1) / SCAN_BLK)   // 98

// Device-global scratch (no dynamic allocation allowed)
__device__ int    g_off[N_NODES + 1];
__device__ int    g_pos[N_NODES];
__device__ int    g_psum[128];
__device__ int2   g_edge[N_EDGES];
__device__ __half g_Xh [(size_t)NPAD * IN_DIM];   // fp16 copy of X
__device__ __half g_W1h[HID * IN_DIM];
__device__ __half g_W2h[HID * HID];
__device__ __half g_W3h[HID * HID];
__device__ __half g_T  [(size_t)N_NODES * HID];   // linear output (pre-SpMM)
__device__ __half g_X1h[(size_t)NPAD * HID];
__device__ __half g_X2h[(size_t)NPAD * HID];
__device__ __half g_X3h[(size_t)NPAD * HID];
__device__ float  g_pool[N_GRAPHS * HID];         // raw sums (scaled in head)

// ---------------------------------------------------------------------------
// Convert X (fp32) -> g_Xh (fp16), zero pad rows. 4 elems/thread.
// ---------------------------------------------------------------------------
__global__ void convert_x_kernel(const float4* __restrict__ X4, uint2* __restrict__ out) {
    int i = blockIdx.x * blockDim.x + threadIdx.x;
    if (i >= NPAD * IN_DIM / 4) return;
    int row = i >> 5;                       // 32 float4 per 128-wide row
    float4 v = (row < N_NODES) ? X4[i] : make_float4(0.f, 0.f, 0.f, 0.f);
    __half2 h0 = __floats2half2_rn(v.x, v.y);
    __half2 h1 = __floats2half2_rn(v.z, v.w);
    out[i] = make_uint2(*(unsigned*)&h0, *(unsigned*)&h1);
}

// Convert the three weight matrices to fp16 (tiny)
__global__ void convert_w_kernel(const float* __restrict__ W1,
                                 const float* __restrict__ W2,
                                 const float* __restrict__ W3,
                                 __half* __restrict__ o1,
                                 __half* __restrict__ o2,
                                 __half* __restrict__ o3) {
    int i = blockIdx.x * blockDim.x + threadIdx.x;
    if (i < HID * IN_DIM) o1[i] = __float2half(W1[i]);
    if (i < HID * HID) {
        o2[i] = __float2half(W2[i]);
        o3[i] = __float2half(W3[i]);
    }
}

// ---------------------------------------------------------------------------
// Tensor-core linear: out[i,h] = (half)(bias[h] + sum_k A[i,k] * W[h,k])
// ---------------------------------------------------------------------------
#define CS_LD 72   // 64 + 8 pad; 72*4B = 288B, multiple of 16B (wmma ldm req)

template<int K>
__global__ void linear_wmma_kernel(const __half* __restrict__ A,
                                   const __half* __restrict__ Wh,
                                   const float* __restrict__ bias,
                                   __half* __restrict__ out) {
    __shared__ float Cs[64 * CS_LD];

    const int w    = threadIdx.x >> 5;        // 0..7
    const int r0   = blockIdx.x * 64;
    const int trow = (w >> 1) << 4;           // 0,16,32,48
    const int tcol = (w & 1) << 5;            // 0,32

    wmma::fragment<wmma::accumulator, 16, 16, 16, float> c0, c1;
    wmma::fill_fragment(c0, 0.0f);
    wmma::fill_fragment(c1, 0.0f);
    wmma::fragment<wmma::matrix_a, 16, 16, 16, __half, wmma::row_major> a;
    wmma::fragment<wmma::matrix_b, 16, 16, 16, __half, wmma::col_major> b0, b1;

    const __half* Ap = A + (size_t)(r0 + trow) * K;
#pragma unroll
    for (int k = 0; k < K; k += 16) {
        wmma::load_matrix_sync(a, Ap + k, K);
        wmma::load_matrix_sync(b0, Wh + (size_t)tcol * K + k, K);
        wmma::load_matrix_sync(b1, Wh + (size_t)(tcol + 16) * K + k, K);
        wmma::mma_sync(c0, a, b0, c0);
        wmma::mma_sync(c1, a, b1, c1);
    }
    wmma::store_matrix_sync(&Cs[trow * CS_LD + tcol],      c0, CS_LD, wmma::mem_row_major);
    wmma::store_matrix_sync(&Cs[trow * CS_LD + tcol + 16], c1, CS_LD, wmma::mem_row_major);
    __syncthreads();

    // Epilogue: each thread handles 16 output elems (quarter row)
    const int lr = threadIdx.x >> 2;          // 0..63
    const int cc = (threadIdx.x & 3) << 4;    // 0,16,32,48
    const int r  = r0 + lr;
    if (r < N_NODES) {
        const float* cp = &Cs[lr * CS_LD + cc];
        __half2 h[8];
#pragma unroll
        for (int j = 0; j < 8; j++) {
            float x = cp[2 * j]     + bias[cc + 2 * j];
            float y = cp[2 * j + 1] + bias[cc + 2 * j + 1];
            h[j] = __floats2half2_rn(x, y);
        }
        uint4* op = (uint4*)(out + (size_t)r * HID + cc);
        op[0] = make_uint4(*(unsigned*)&h[0], *(unsigned*)&h[1],
                           *(unsigned*)&h[2], *(unsigned*)&h[3]);
        op[1] = make_uint4(*(unsigned*)&h[4], *(unsigned*)&h[5],
                           *(unsigned*)&h[6], *(unsigned*)&h[7]);
    }
}

// ---------------------------------------------------------------------------
// CSR build step 1: histogram of row indices (4 edges/thread)
// ---------------------------------------------------------------------------
__global__ void hist_kernel(const int4* __restrict__ rows4, int* __restrict__ cnt) {
    int i = blockIdx.x * blockDim.x + threadIdx.x;
    if (i < N_EDGES / 4) {
        int4 r = rows4[i];
        atomicAdd(&cnt[r.x], 1);
        atomicAdd(&cnt[r.y], 1);
        atomicAdd(&cnt[r.z], 1);
        atomicAdd(&cnt[r.w], 1);
    }
}

// CSR build step 2a: per-block exclusive scan (in place), emit block sums
__global__ void scan_block_kernel(int* __restrict__ data, int* __restrict__ bsums) {
    __shared__ int sh[SCAN_BLK];
    int i = blockIdx.x * SCAN_BLK + threadIdx.x;
    int v = (i < N_NODES) ? data[i] : 0;
    sh[threadIdx.x] = v;
    __syncthreads();
    for (int d = 1; d < SCAN_BLK; d <<= 1) {
        int t = (threadIdx.x >= d) ? sh[threadIdx.x - d] : 0;
        __syncthreads();
        sh[threadIdx.x] += t;
        __syncthreads();
    }
    if (i < N_NODES) data[i] = sh[threadIdx.x] - v;   // exclusive
    if (threadIdx.x == SCAN_BLK - 1) bsums[blockIdx.x] = sh[SCAN_BLK - 1];
}

// CSR build step 2b: exclusive scan of the block sums (single block)
__global__ void scan_top_kernel(int* __restrict__ bsums) {
    __shared__ int sh[128];
    int v = (threadIdx.x < N_SCAN_BLOCKS) ? bsums[threadIdx.x] : 0;
    sh[threadIdx.x] = v;
    __syncthreads();
    for (int d = 1; d < 128; d <<= 1) {
        int t = (threadIdx.x >= d) ? sh[threadIdx.x - d] : 0;
        __syncthreads();
        sh[threadIdx.x] += t;
        __syncthreads();
    }
    if (threadIdx.x < N_SCAN_BLOCKS) bsums[threadIdx.x] = sh[threadIdx.x] - v;
}

// CSR build step 2c: add block offsets, init scatter cursors, seal tail
__global__ void add_off_kernel(int* __restrict__ data, const int* __restrict__ bsums,
                               int* __restrict__ pos) {
    int i = blockIdx.x * blockDim.x + threadIdx.x;
    if (i < N_NODES) {
        int o = data[i] + bsums[i >> 10];
        data[i] = o;
        pos[i] = o;
    }
    if (i == 0) data[N_NODES] = N_EDGES;
}

// CSR build step 3: scatter edges into CSR order (4 edges/thread)
__global__ void scatter_kernel(const int4* __restrict__ rows4,
                               const int4* __restrict__ cols4,
                               const float4* __restrict__ vals4,
                               int* __restrict__ pos, int2* __restrict__ edge) {
    int i = blockIdx.x * blockDim.x + threadIdx.x;
    if (i >= N_EDGES / 4) return;
    int4 r = rows4[i];
    int4 c = cols4[i];
    float4 v = vals4[i];
    int p;
    p = atomicAdd(&pos[r.x], 1); edge[p] = make_int2(c.x, __float_as_int(v.x));
    p = atomicAdd(&pos[r.y], 1); edge[p] = make_int2(c.y, __float_as_int(v.y));
    p = atomicAdd(&pos[r.z], 1); edge[p] = make_int2(c.z, __float_as_int(v.z));
    p = atomicAdd(&pos[r.w], 1); edge[p] = make_int2(c.w, __float_as_int(v.w));
}

// ---------------------------------------------------------------------------
// CSR SpMM with fused ReLU: out[r,:] = relu(sum_e val * H[col,:])
// 2 rows per warp: lanes 0-15 -> row A, lanes 16-31 -> row B.
// Lane owns 4 channels (uint2 = 8B of fp16). width-16 shfl broadcasts one
// edge per row per step -> 1 SHFL/edge, 0.5 LDG/edge. fp32 accumulate.
// ---------------------------------------------------------------------------
__global__ void spmm_csr_kernel(const int* __restrict__ off,
                                const int2* __restrict__ edge,
                                const __half* __restrict__ H,
                                __half* __restrict__ out) {
    const int lane = threadIdx.x & 31;
    const int hl   = lane & 15;               // lane within half-warp
    const int warp = threadIdx.x >> 5;
    const int r = (blockIdx.x * (blockDim.x >> 5) + warp) * 2 + (lane >> 4);
    // grid sized so r < N_NODES always (100000 = 6250 * 16)

    const int s = off[r];
    const int e = off[r + 1];
    int nIter = (e - s + 15) >> 4;
    int nOther = __shfl_xor_sync(0xffffffffu, nIter, 16);
    const int nMax = max(nIter, nOther);

    float4 acc = make_float4(0.f, 0.f, 0.f, 0.f);

    for (int it = 0; it < nMax; it++) {
        int idx = s + (it << 4) + hl;
        int2 ev = (idx < e) ? edge[idx] : make_int2(0, 0);
#pragma unroll
        for (int j = 0; j < 16; j++) {
            int   c = __shfl_sync(0xffffffffu, ev.x, j, 16);
            float v = __int_as_float(__shfl_sync(0xffffffffu, ev.y, j, 16));
            uint2 raw = *(const uint2*)(H + (size_t)c * HID + (hl << 2));
            float2 f0 = __half22float2(*(__half2*)&raw.x);
            float2 f1 = __half22float2(*(__half2*)&raw.y);
            acc.x += v * f0.x;
            acc.y += v * f0.y;
            acc.z += v * f1.x;
            acc.w += v * f1.y;
        }
    }

    __half2 h0 = __floats2half2_rn(fmaxf(acc.x, 0.f), fmaxf(acc.y, 0.f));
    __half2 h1 = __floats2half2_rn(fmaxf(acc.z, 0.f), fmaxf(acc.w, 0.f));
    *(uint2*)(out + (size_t)r * HID + (hl << 2)) = make_uint2(*(unsigned*)&h0, *(unsigned*)&h1);
}

// ---------------------------------------------------------------------------
// Global mean pool, partials: 4 blocks per graph, raw sums via atomics.
// Scaling (1/(3*cnt)) happens in head_kernel.
// ---------------------------------------------------------------------------
__global__ void pool_kernel(const __half* __restrict__ X1,
                            const __half* __restrict__ X2,
                            const __half* __restrict__ X3,
                            const int* __restrict__ batch,
                            float* __restrict__ pool) {
    const int g = blockIdx.x >> 2;
    const int part = blockIdx.x & 3;
    __shared__ int bnd[2];
    if (threadIdx.x < 2) {
        int target = g + threadIdx.x;
        int lo = 0, hi = N_NODES;
        while (lo < hi) { int m = (lo + hi) >> 1; if (batch[m] < target) lo = m + 1; else hi = m; }
        bnd[threadIdx.x] = lo;
    }
    __syncthreads();
    const int gs = bnd[0], ge = bnd[1];
    const int len = ge - gs;
    const int s0 = gs + ((len * part) >> 2);
    const int s1 = gs + ((len * (part + 1)) >> 2);

    const int lane = threadIdx.x & 31;
    const int w = threadIdx.x >> 5;          // 8 warps

    float2 acc = make_float2(0.0f, 0.0f);
    for (int i = s0 + w; i < s1; i += 8) {
        size_t o = (size_t)i * HID;
        float2 a = __half22float2(((const __half2*)(X1 + o))[lane]);
        float2 b = __half22float2(((const __half2*)(X2 + o))[lane]);
        float2 c = __half22float2(((const __half2*)(X3 + o))[lane]);
        acc.x += a.x + b.x + c.x;
        acc.y += a.y + b.y + c.y;
    }

    __shared__ float2 sh[8][32];
    sh[w][lane] = acc;
    __syncthreads();
    if (w == 0) {
        float2 t = sh[0][lane];
#pragma unroll
        for (int k = 1; k < 8; k++) { t.x += sh[k][lane].x; t.y += sh[k][lane].y; }
        atomicAdd(&pool[g * HID + 2 * lane],     t.x);
        atomicAdd(&pool[g * HID + 2 * lane + 1], t.y);
    }
}

// ---------------------------------------------------------------------------
// Head: scale pooled sums, linear + softmax. One thread per graph.
// ---------------------------------------------------------------------------
__global__ void head_kernel(const float* __restrict__ pool,
                            const int* __restrict__ batch,
                            const float* __restrict__ Wout,
                            const float* __restrict__ bout,
                            float* __restrict__ out) {
    int g = threadIdx.x;
    if (g >= N_GRAPHS) return;

    // count nodes in graph g via binary search on sorted batch
    int lo = 0, hi = N_NODES;
    while (lo < hi) { int m = (lo + hi) >> 1; if (batch[m] < g) lo = m + 1; else hi = m; }
    int s0 = lo;
    lo = 0; hi = N_NODES;
    while (lo < hi) { int m = (lo + hi) >> 1; if (batch[m] < g + 1) lo = m + 1; else hi = m; }
    float cnt = fmaxf((float)(lo - s0), 1.0f);
    float sc = 1.0f / (3.0f * cnt);

    float logits[OUT_DIM];
    float mx = -3.0e38f;
#pragma unroll
    for (int j = 0; j < OUT_DIM; j++) {
        float s = bout[j];
        for (int k = 0; k < HID; k++)
            s += pool[g * HID + k] * sc * Wout[j * HID + k];
        logits[j] = s;
        mx = fmaxf(mx, s);
    }
    float sum = 0.0f;
#pragma unroll
    for (int j = 0; j < OUT_DIM; j++) {
        float e = expf(logits[j] - mx);
        logits[j] = e;
        sum += e;
    }
    float isum = 1.0f / sum;
#pragma unroll
    for (int j = 0; j < OUT_DIM; j++)
        out[g * OUT_DIM + j] = logits[j] * isum;
}

// ---------------------------------------------------------------------------
extern "C" void kernel_launch(void* const* d_in, const int* in_sizes, int n_in,
                              void* d_out, int out_size) {
    const float* X    = (const float*)d_in[0];
    const float* vals = (const float*)d_in[1];
    const float* W1   = (const float*)d_in[2];
    const float* b1   = (const float*)d_in[3];
    const float* W2   = (const float*)d_in[4];
    const float* b2   = (const float*)d_in[5];
    const float* W3   = (const float*)d_in[6];
    const float* b3   = (const float*)d_in[7];
    const float* Wout = (const float*)d_in[8];
    const float* bout = (const float*)d_in[9];
    const int* rows   = (const int*)d_in[10];
    const int* cols   = (const int*)d_in[11];
    const int* batch  = (const int*)d_in[12];
    float* out = (float*)d_out;

    void *pOff, *pPos, *pPsum, *pEdge, *pXh, *pW1h, *pW2h, *pW3h;
    void *pT, *p1, *p2, *p3, *pp;
    cudaGetSymbolAddress(&pOff,  g_off);
    cudaGetSymbolAddress(&pPos,  g_pos);
    cudaGetSymbolAddress(&pPsum, g_psum);
    cudaGetSymbolAddress(&pEdge, g_edge);
    cudaGetSymbolAddress(&pXh,  g_Xh);
    cudaGetSymbolAddress(&pW1h, g_W1h);
    cudaGetSymbolAddress(&pW2h, g_W2h);
    cudaGetSymbolAddress(&pW3h, g_W3h);
    cudaGetSymbolAddress(&pT, g_T);
    cudaGetSymbolAddress(&p1, g_X1h);
    cudaGetSymbolAddress(&p2, g_X2h);
    cudaGetSymbolAddress(&p3, g_X3h);
    cudaGetSymbolAddress(&pp, g_pool);

    // ---- fp16 conversions ----
    const int cx_grid = (NPAD * IN_DIM / 4 + 255) / 256;
    convert_x_kernel<<<cx_grid, 256>>>((const float4*)X, (uint2*)pXh);
    convert_w_kernel<<<32, 256>>>(W1, W2, W3, (__half*)pW1h, (__half*)pW2h, (__half*)pW3h);

    // ---- CSR build ----
    cudaMemsetAsync(pOff, 0, (size_t)(N_NODES + 1) * sizeof(int));
    cudaMemsetAsync(pp, 0, (size_t)N_GRAPHS * HID * sizeof(float));
    const int e4grid = (N_EDGES / 4 + 255) / 256;   // 3125
    hist_kernel<<<e4grid, 256>>>((const int4*)rows, (int*)pOff);
    scan_block_kernel<<<N_SCAN_BLOCKS, SCAN_BLK>>>((int*)pOff, (int*)pPsum);
    scan_top_kernel<<<1, 128>>>((int*)pPsum);
    add_off_kernel<<<(N_NODES + 255) / 256, 256>>>((int*)pOff, (int*)pPsum, (int*)pPos);
    scatter_kernel<<<e4grid, 256>>>((const int4*)rows, (const int4*)cols,
                                    (const float4*)vals, (int*)pPos, (int2*)pEdge);

    const int gemm_grid = NPAD / 64;                  // 1563
    const int spmm_grid = N_NODES / 16;               // 6250 (8 warps x 2 rows)

    // Layer 1
    linear_wmma_kernel<IN_DIM><<<gemm_grid, 256>>>((const __half*)pXh, (const __half*)pW1h, b1, (__half*)pT);
    spmm_csr_kernel<<<spmm_grid, 256>>>((int*)pOff, (const int2*)pEdge, (const __half*)pT, (__half*)p1);
    // Layer 2
    linear_wmma_kernel<HID><<<gemm_grid, 256>>>((const __half*)p1, (const __half*)pW2h, b2, (__half*)pT);
    spmm_csr_kernel<<<spmm_grid, 256>>>((int*)pOff, (const int2*)pEdge, (const __half*)pT, (__half*)p2);
    // Layer 3
    linear_wmma_kernel<HID><<<gemm_grid, 256>>>((const __half*)p2, (const __half*)pW3h, b3, (__half*)pT);
    spmm_csr_kernel<<<spmm_grid, 256>>>((int*)pOff, (const int2*)pEdge, (const __half*)pT, (__half*)p3);
    // Pool + head
    pool_kernel<<<N_GRAPHS * 4, 256>>>((const __half*)p1, (const __half*)p2, (const __half*)p3, batch, (float*)pp);
    head_kernel<<<1, 64>>>((float*)pp, batch, Wout, bout, out);
}

// round 15
// speedup vs baseline: 4.4004x; 1.0747x over previous
#include <cuda_runtime.h>
#include <cuda_fp16.h>
#include <mma.h>

using namespace nvcuda;

#define N_NODES 100000
#define NPAD    100032          // 64 * 1563, padded row count for wmma tiles
#define N_EDGES 3200000
#define IN_DIM  128
#define HID     64
#define N_GRAPHS 64
#define OUT_DIM 10

#define SCAN_BLK 1024
#define N_SCAN_BLOCKS ((N_NODES + SCAN_BLK - 1) / SCAN_BLK)   // 98

// Device-global scratch (no dynamic allocation allowed)
__device__ int    g_off[N_NODES + 1];
__device__ int    g_pos[N_NODES];
__device__ int    g_psum[128];
__device__ int2   g_edge[N_EDGES];
__device__ __half g_Xh [(size_t)NPAD * IN_DIM];   // fp16 copy of X
__device__ __half g_W1h[HID * IN_DIM];
__device__ __half g_W2h[HID * HID];
__device__ __half g_W3h[HID * HID];
__device__ __half g_T  [(size_t)N_NODES * HID];   // linear output (pre-SpMM)
__device__ __half g_X1h[(size_t)NPAD * HID];
__device__ __half g_X2h[(size_t)NPAD * HID];
__device__ __half g_X3h[(size_t)NPAD * HID];
__device__ float  g_pool[N_GRAPHS * HID];         // raw sums (scaled in head)

// ---------------------------------------------------------------------------
// Convert X (fp32) -> g_Xh (fp16), zero pad rows. 4 elems/thread.
// ---------------------------------------------------------------------------
__global__ void convert_x_kernel(const float4* __restrict__ X4, uint2* __restrict__ out) {
    int i = blockIdx.x * blockDim.x + threadIdx.x;
    if (i >= NPAD * IN_DIM / 4) return;
    int row = i >> 5;                       // 32 float4 per 128-wide row
    float4 v = (row < N_NODES) ? X4[i] : make_float4(0.f, 0.f, 0.f, 0.f);
    __half2 h0 = __floats2half2_rn(v.x, v.y);
    __half2 h1 = __floats2half2_rn(v.z, v.w);
    out[i] = make_uint2(*(unsigned*)&h0, *(unsigned*)&h1);
}

// Convert the three weight matrices to fp16 (tiny)
__global__ void convert_w_kernel(const float* __restrict__ W1,
                                 const float* __restrict__ W2,
                                 const float* __restrict__ W3,
                                 __half* __restrict__ o1,
                                 __half* __restrict__ o2,
                                 __half* __restrict__ o3) {
    int i = blockIdx.x * blockDim.x + threadIdx.x;
    if (i < HID * IN_DIM) o1[i] = __float2half(W1[i]);
    if (i < HID * HID) {
        o2[i] = __float2half(W2[i]);
        o3[i] = __float2half(W3[i]);
    }
}

// ---------------------------------------------------------------------------
// Tensor-core linear: out[i,h] = (half)(bias[h] + sum_k A[i,k] * W[h,k])
// ---------------------------------------------------------------------------
#define CS_LD 72   // 64 + 8 pad; 72*4B = 288B, multiple of 16B (wmma ldm req)

template<int K>
__global__ void linear_wmma_kernel(const __half* __restrict__ A,
                                   const __half* __restrict__ Wh,
                                   const float* __restrict__ bias,
                                   __half* __restrict__ out) {
    __shared__ float Cs[64 * CS_LD];

    const int w    = threadIdx.x >> 5;        // 0..7
    const int r0   = blockIdx.x * 64;
    const int trow = (w >> 1) << 4;           // 0,16,32,48
    const int tcol = (w & 1) << 5;            // 0,32

    wmma::fragment<wmma::accumulator, 16, 16, 16, float> c0, c1;
    wmma::fill_fragment(c0, 0.0f);
    wmma::fill_fragment(c1, 0.0f);
    wmma::fragment<wmma::matrix_a, 16, 16, 16, __half, wmma::row_major> a;
    wmma::fragment<wmma::matrix_b, 16, 16, 16, __half, wmma::col_major> b0, b1;

    const __half* Ap = A + (size_t)(r0 + trow) * K;
#pragma unroll
    for (int k = 0; k < K; k += 16) {
        wmma::load_matrix_sync(a, Ap + k, K);
        wmma::load_matrix_sync(b0, Wh + (size_t)tcol * K + k, K);
        wmma::load_matrix_sync(b1, Wh + (size_t)(tcol + 16) * K + k, K);
        wmma::mma_sync(c0, a, b0, c0);
        wmma::mma_sync(c1, a, b1, c1);
    }
    wmma::store_matrix_sync(&Cs[trow * CS_LD + tcol],      c0, CS_LD, wmma::mem_row_major);
    wmma::store_matrix_sync(&Cs[trow * CS_LD + tcol + 16], c1, CS_LD, wmma::mem_row_major);
    __syncthreads();

    // Epilogue: each thread handles 16 output elems (quarter row)
    const int lr = threadIdx.x >> 2;          // 0..63
    const int cc = (threadIdx.x & 3) << 4;    // 0,16,32,48
    const int r  = r0 + lr;
    if (r < N_NODES) {
        const float* cp = &Cs[lr * CS_LD + cc];
        __half2 h[8];
#pragma unroll
        for (int j = 0; j < 8; j++) {
            float x = cp[2 * j]     + bias[cc + 2 * j];
            float y = cp[2 * j + 1] + bias[cc + 2 * j + 1];
            h[j] = __floats2half2_rn(x, y);
        }
        uint4* op = (uint4*)(out + (size_t)r * HID + cc);
        op[0] = make_uint4(*(unsigned*)&h[0], *(unsigned*)&h[1],
                           *(unsigned*)&h[2], *(unsigned*)&h[3]);
        op[1] = make_uint4(*(unsigned*)&h[4], *(unsigned*)&h[5],
                           *(unsigned*)&h[6], *(unsigned*)&h[7]);
    }
}

// ---------------------------------------------------------------------------
// CSR build step 1: histogram of row indices (4 edges/thread)
// ---------------------------------------------------------------------------
__global__ void hist_kernel(const int4* __restrict__ rows4, int* __restrict__ cnt) {
    int i = blockIdx.x * blockDim.x + threadIdx.x;
    if (i < N_EDGES / 4) {
        int4 r = rows4[i];
        atomicAdd(&cnt[r.x], 1);
        atomicAdd(&cnt[r.y], 1);
        atomicAdd(&cnt[r.z], 1);
        atomicAdd(&cnt[r.w], 1);
    }
}

// CSR build step 2a: per-block exclusive scan (in place), emit block sums
__global__ void scan_block_kernel(int* __restrict__ data, int* __restrict__ bsums) {
    __shared__ int sh[SCAN_BLK];
    int i = blockIdx.x * SCAN_BLK + threadIdx.x;
    int v = (i < N_NODES) ? data[i] : 0;
    sh[threadIdx.x] = v;
    __syncthreads();
    for (int d = 1; d < SCAN_BLK; d <<= 1) {
        int t = (threadIdx.x >= d) ? sh[threadIdx.x - d] : 0;
        __syncthreads();
        sh[threadIdx.x] += t;
        __syncthreads();
    }
    if (i < N_NODES) data[i] = sh[threadIdx.x] - v;   // exclusive
    if (threadIdx.x == SCAN_BLK - 1) bsums[blockIdx.x] = sh[SCAN_BLK - 1];
}

// CSR build step 2b: exclusive scan of the block sums (single block)
__global__ void scan_top_kernel(int* __restrict__ bsums) {
    __shared__ int sh[128];
    int v = (threadIdx.x < N_SCAN_BLOCKS) ? bsums[threadIdx.x] : 0;
    sh[threadIdx.x] = v;
    __syncthreads();
    for (int d = 1; d < 128; d <<= 1) {
        int t = (threadIdx.x >= d) ? sh[threadIdx.x - d] : 0;
        __syncthreads();
        sh[threadIdx.x] += t;
        __syncthreads();
    }
    if (threadIdx.x < N_SCAN_BLOCKS) bsums[threadIdx.x] = sh[threadIdx.x] - v;
}

// CSR build step 2c: add block offsets, init scatter cursors, seal tail
__global__ void add_off_kernel(int* __restrict__ data, const int* __restrict__ bsums,
                               int* __restrict__ pos) {
    int i = blockIdx.x * blockDim.x + threadIdx.x;
    if (i < N_NODES) {
        int o = data[i] + bsums[i >> 10];
        data[i] = o;
        pos[i] = o;
    }
    if (i == 0) data[N_NODES] = N_EDGES;
}

// CSR build step 3: scatter edges into CSR order (4 edges/thread)
__global__ void scatter_kernel(const int4* __restrict__ rows4,
                               const int4* __restrict__ cols4,
                               const float4* __restrict__ vals4,
                               int* __restrict__ pos, int2* __restrict__ edge) {
    int i = blockIdx.x * blockDim.x + threadIdx.x;
    if (i >= N_EDGES / 4) return;
    int4 r = rows4[i];
    int4 c = cols4[i];
    float4 v = vals4[i];
    int p;
    p = atomicAdd(&pos[r.x], 1); edge[p] = make_int2(c.x, __float_as_int(v.x));
    p = atomicAdd(&pos[r.y], 1); edge[p] = make_int2(c.y, __float_as_int(v.y));
    p = atomicAdd(&pos[r.z], 1); edge[p] = make_int2(c.z, __float_as_int(v.z));
    p = atomicAdd(&pos[r.w], 1); edge[p] = make_int2(c.w, __float_as_int(v.w));
}

// ---------------------------------------------------------------------------
// CSR SpMM with fused ReLU: out[r,:] = relu(sum_e val * H[col,:])
// 4 rows per warp: quarter q = lane>>3 owns row r0+q; 8 lanes per row,
// each lane owns 8 channels (uint4 = 16B fp16). width-8 shfl broadcasts one
// edge per row per step -> 0.5 SHFL/edge, 0.25 LDG/edge. HFMA2 fp16
// accumulation (no cvt unpack): ~2.6 warp-instr/edge.
// ---------------------------------------------------------------------------
__global__ void spmm_csr_kernel(const int* __restrict__ off,
                                const int2* __restrict__ edge,
                                const __half* __restrict__ H,
                                __half* __restrict__ out) {
    const int lane = threadIdx.x & 31;
    const int hl   = lane & 7;                // lane within 8-lane group
    const int warp = threadIdx.x >> 5;
    const int r = (blockIdx.x * (blockDim.x >> 5) + warp) * 4 + (lane >> 3);
    // grid sized so r < N_NODES always (100000 = 3125 * 32)

    const int s = off[r];
    const int e = off[r + 1];
    int nIter = (e - s + 7) >> 3;
    nIter = max(nIter, __shfl_xor_sync(0xffffffffu, nIter, 8));
    nIter = max(nIter, __shfl_xor_sync(0xffffffffu, nIter, 16));

    __half2 acc0 = __float2half2_rn(0.f);
    __half2 acc1 = acc0, acc2 = acc0, acc3 = acc0;

    for (int it = 0; it < nIter; it++) {
        int idx = s + (it << 3) + hl;
        int2 ev = (idx < e) ? edge[idx] : make_int2(0, 0);   // val=0 -> no-op
#pragma unroll
        for (int j = 0; j < 8; j++) {
            int   c = __shfl_sync(0xffffffffu, ev.x, j, 8);
            float v = __int_as_float(__shfl_sync(0xffffffffu, ev.y, j, 8));
            __half2 vv = __floats2half2_rn(v, v);
            uint4 raw = *((const uint4*)(H + (size_t)c * HID) + hl);
            acc0 = __hfma2(*(__half2*)&raw.x, vv, acc0);
            acc1 = __hfma2(*(__half2*)&raw.y, vv, acc1);
            acc2 = __hfma2(*(__half2*)&raw.z, vv, acc2);
            acc3 = __hfma2(*(__half2*)&raw.w, vv, acc3);
        }
    }

    const __half2 z = __float2half2_rn(0.f);
    acc0 = __hmax2(acc0, z);
    acc1 = __hmax2(acc1, z);
    acc2 = __hmax2(acc2, z);
    acc3 = __hmax2(acc3, z);
    uint4 o;
    o.x = *(unsigned*)&acc0; o.y = *(unsigned*)&acc1;
    o.z = *(unsigned*)&acc2; o.w = *(unsigned*)&acc3;
    *((uint4*)(out + (size_t)r * HID) + hl) = o;
}

// ---------------------------------------------------------------------------
// Global mean pool, partials: 4 blocks per graph, raw sums via atomics.
// Scaling (1/(3*cnt)) happens in head_kernel.
// ---------------------------------------------------------------------------
__global__ void pool_kernel(const __half* __restrict__ X1,
                            const __half* __restrict__ X2,
                            const __half* __restrict__ X3,
                            const int* __restrict__ batch,
                            float* __restrict__ pool) {
    const int g = blockIdx.x >> 2;
    const int part = blockIdx.x & 3;
    __shared__ int bnd[2];
    if (threadIdx.x < 2) {
        int target = g + threadIdx.x;
        int lo = 0, hi = N_NODES;
        while (lo < hi) { int m = (lo + hi) >> 1; if (batch[m] < target) lo = m + 1; else hi = m; }
        bnd[threadIdx.x] = lo;
    }
    __syncthreads();
    const int gs = bnd[0], ge = bnd[1];
    const int len = ge - gs;
    const int s0 = gs + ((len * part) >> 2);
    const int s1 = gs + ((len * (part + 1)) >> 2);

    const int lane = threadIdx.x & 31;
    const int w = threadIdx.x >> 5;          // 8 warps

    float2 acc = make_float2(0.0f, 0.0f);
    for (int i = s0 + w; i < s1; i += 8) {
        size_t o = (size_t)i * HID;
        float2 a = __half22float2(((const __half2*)(X1 + o))[lane]);
        float2 b = __half22float2(((const __half2*)(X2 + o))[lane]);
        float2 c = __half22float2(((const __half2*)(X3 + o))[lane]);
        acc.x += a.x + b.x + c.x;
        acc.y += a.y + b.y + c.y;
    }

    __shared__ float2 sh[8][32];
    sh[w][lane] = acc;
    __syncthreads();
    if (w == 0) {
        float2 t = sh[0][lane];
#pragma unroll
        for (int k = 1; k < 8; k++) { t.x += sh[k][lane].x; t.y += sh[k][lane].y; }
        atomicAdd(&pool[g * HID + 2 * lane],     t.x);
        atomicAdd(&pool[g * HID + 2 * lane + 1], t.y);
    }
}

// ---------------------------------------------------------------------------
// Head: scale pooled sums, linear + softmax. One thread per graph.
// ---------------------------------------------------------------------------
__global__ void head_kernel(const float* __restrict__ pool,
                            const int* __restrict__ batch,
                            const float* __restrict__ Wout,
                            const float* __restrict__ bout,
                            float* __restrict__ out) {
    int g = threadIdx.x;
    if (g >= N_GRAPHS) return;

    // count nodes in graph g via binary search on sorted batch
    int lo = 0, hi = N_NODES;
    while (lo < hi) { int m = (lo + hi) >> 1; if (batch[m] < g) lo = m + 1; else hi = m; }
    int s0 = lo;
    lo = 0; hi = N_NODES;
    while (lo < hi) { int m = (lo + hi) >> 1; if (batch[m] < g + 1) lo = m + 1; else hi = m; }
    float cnt = fmaxf((float)(lo - s0), 1.0f);
    float sc = 1.0f / (3.0f * cnt);

    float logits[OUT_DIM];
    float mx = -3.0e38f;
#pragma unroll
    for (int j = 0; j < OUT_DIM; j++) {
        float s = bout[j];
        for (int k = 0; k < HID; k++)
            s += pool[g * HID + k] * sc * Wout[j * HID + k];
        logits[j] = s;
        mx = fmaxf(mx, s);
    }
    float sum = 0.0f;
#pragma unroll
    for (int j = 0; j < OUT_DIM; j++) {
        float e = expf(logits[j] - mx);
        logits[j] = e;
        sum += e;
    }
    float isum = 1.0f / sum;
#pragma unroll
    for (int j = 0; j < OUT_DIM; j++)
        out[g * OUT_DIM + j] = logits[j] * isum;
}

// ---------------------------------------------------------------------------
extern "C" void kernel_launch(void* const* d_in, const int* in_sizes, int n_in,
                              void* d_out, int out_size) {
    const float* X    = (const float*)d_in[0];
    const float* vals = (const float*)d_in[1];
    const float* W1   = (const float*)d_in[2];
    const float* b1   = (const float*)d_in[3];
    const float* W2   = (const float*)d_in[4];
    const float* b2   = (const float*)d_in[5];
    const float* W3   = (const float*)d_in[6];
    const float* b3   = (const float*)d_in[7];
    const float* Wout = (const float*)d_in[8];
    const float* bout = (const float*)d_in[9];
    const int* rows   = (const int*)d_in[10];
    const int* cols   = (const int*)d_in[11];
    const int* batch  = (const int*)d_in[12];
    float* out = (float*)d_out;

    void *pOff, *pPos, *pPsum, *pEdge, *pXh, *pW1h, *pW2h, *pW3h;
    void *pT, *p1, *p2, *p3, *pp;
    cudaGetSymbolAddress(&pOff,  g_off);
    cudaGetSymbolAddress(&pPos,  g_pos);
    cudaGetSymbolAddress(&pPsum, g_psum);
    cudaGetSymbolAddress(&pEdge, g_edge);
    cudaGetSymbolAddress(&pXh,  g_Xh);
    cudaGetSymbolAddress(&pW1h, g_W1h);
    cudaGetSymbolAddress(&pW2h, g_W2h);
    cudaGetSymbolAddress(&pW3h, g_W3h);
    cudaGetSymbolAddress(&pT, g_T);
    cudaGetSymbolAddress(&p1, g_X1h);
    cudaGetSymbolAddress(&p2, g_X2h);
    cudaGetSymbolAddress(&p3, g_X3h);
    cudaGetSymbolAddress(&pp, g_pool);

    // ---- fp16 conversions ----
    const int cx_grid = (NPAD * IN_DIM / 4 + 255) / 256;
    convert_x_kernel<<<cx_grid, 256>>>((const float4*)X, (uint2*)pXh);
    convert_w_kernel<<<32, 256>>>(W1, W2, W3, (__half*)pW1h, (__half*)pW2h, (__half*)pW3h);

    // ---- CSR build ----
    cudaMemsetAsync(pOff, 0, (size_t)(N_NODES + 1) * sizeof(int));
    cudaMemsetAsync(pp, 0, (size_t)N_GRAPHS * HID * sizeof(float));
    const int e4grid = (N_EDGES / 4 + 255) / 256;   // 3125
    hist_kernel<<<e4grid, 256>>>((const int4*)rows, (int*)pOff);
    scan_block_kernel<<<N_SCAN_BLOCKS, SCAN_BLK>>>((int*)pOff, (int*)pPsum);
    scan_top_kernel<<<1, 128>>>((int*)pPsum);
    add_off_kernel<<<(N_NODES + 255) / 256, 256>>>((int*)pOff, (int*)pPsum, (int*)pPos);
    scatter_kernel<<<e4grid, 256>>>((const int4*)rows, (const int4*)cols,
                                    (const float4*)vals, (int*)pPos, (int2*)pEdge);

    const int gemm_grid = NPAD / 64;                  // 1563
    const int spmm_grid = N_NODES / 32;               // 3125 (8 warps x 4 rows)

    // Layer 1
    linear_wmma_kernel<IN_DIM><<<gemm_grid, 256>>>((const __half*)pXh, (const __half*)pW1h, b1, (__half*)pT);
    spmm_csr_kernel<<<spmm_grid, 256>>>((int*)pOff, (const int2*)pEdge, (const __half*)pT, (__half*)p1);
    // Layer 2
    linear_wmma_kernel<HID><<<gemm_grid, 256>>>((const __half*)p1, (const __half*)pW2h, b2, (__half*)pT);
    spmm_csr_kernel<<<spmm_grid, 256>>>((int*)pOff, (const int2*)pEdge, (const __half*)pT, (__half*)p2);
    // Layer 3
    linear_wmma_kernel<HID><<<gemm_grid, 256>>>((const __half*)p2, (const __half*)pW3h, b3, (__half*)pT);
    spmm_csr_kernel<<<spmm_grid, 256>>>((int*)pOff, (const int2*)pEdge, (const __half*)pT, (__half*)p3);
    // Pool + head
    pool_kernel<<<N_GRAPHS * 4, 256>>>((const __half*)p1, (const __half*)p2, (const __half*)p3, batch, (float*)pp);
    head_kernel<<<1, 64>>>((float*)pp, batch, Wout, bout, out);
}

// round 16
// speedup vs baseline: 4.5346x; 1.0305x over previous
#include <cuda_runtime.h>
#include <cuda_fp16.h>
#include <mma.h>

using namespace nvcuda;

#define N_NODES 100000
#define NPAD    100032          // 64 * 1563, padded row count for wmma tiles
#define N_EDGES 3200000
#define IN_DIM  128
#define HID     64
#define N_GRAPHS 64
#define OUT_DIM 10

#define SCAN_BLK 1024
#define N_SCAN_BLOCKS ((N_NODES + SCAN_BLK - 1) / SCAN_BLK)   // 98

// Device-global scratch (no dynamic allocation allowed)
__device__ int    g_off[N_NODES + 1];
__device__ int    g_pos[N_NODES];
__device__ int    g_psum[128];
__device__ int2   g_edge[N_EDGES];
__device__ __half g_Xh [(size_t)NPAD * IN_DIM];   // fp16 copy of X
__device__ __half g_W1h[HID * IN_DIM];
__device__ __half g_W2h[HID * HID];
__device__ __half g_W3h[HID * HID];
__device__ __half g_T  [(size_t)N_NODES * HID];   // linear output (pre-SpMM)
__device__ __half g_X1h[(size_t)NPAD * HID];
__device__ __half g_X2h[(size_t)NPAD * HID];
__device__ __half g_X3h[(size_t)NPAD * HID];
__device__ float  g_pool[N_GRAPHS * HID];         // raw sums (scaled in head)

// ---------------------------------------------------------------------------
// Convert X (fp32) -> g_Xh (fp16), zero pad rows. 4 elems/thread.
// ---------------------------------------------------------------------------
__global__ void convert_x_kernel(const float4* __restrict__ X4, uint2* __restrict__ out) {
    int i = blockIdx.x * blockDim.x + threadIdx.x;
    if (i >= NPAD * IN_DIM / 4) return;
    int row = i >> 5;                       // 32 float4 per 128-wide row
    float4 v = (row < N_NODES) ? X4[i] : make_float4(0.f, 0.f, 0.f, 0.f);
    __half2 h0 = __floats2half2_rn(v.x, v.y);
    __half2 h1 = __floats2half2_rn(v.z, v.w);
    out[i] = make_uint2(*(unsigned*)&h0, *(unsigned*)&h1);
}

// Convert the three weight matrices to fp16 (tiny)
__global__ void convert_w_kernel(const float* __restrict__ W1,
                                 const float* __restrict__ W2,
                                 const float* __restrict__ W3,
                                 __half* __restrict__ o1,
                                 __half* __restrict__ o2,
                                 __half* __restrict__ o3) {
    int i = blockIdx.x * blockDim.x + threadIdx.x;
    if (i < HID * IN_DIM) o1[i] = __float2half(W1[i]);
    if (i < HID * HID) {
        o2[i] = __float2half(W2[i]);
        o3[i] = __float2half(W3[i]);
    }
}

// ---------------------------------------------------------------------------
// Tensor-core linear: out[i,h] = (half)(bias[h] + sum_k A[i,k] * W[h,k])
// ---------------------------------------------------------------------------
#define CS_LD 72   // 64 + 8 pad; 72*4B = 288B, multiple of 16B (wmma ldm req)

template<int K>
__global__ void linear_wmma_kernel(const __half* __restrict__ A,
                                   const __half* __restrict__ Wh,
                                   const float* __restrict__ bias,
                                   __half* __restrict__ out) {
    __shared__ float Cs[64 * CS_LD];

    const int w    = threadIdx.x >> 5;        // 0..7
    const int r0   = blockIdx.x * 64;
    const int trow = (w >> 1) << 4;           // 0,16,32,48
    const int tcol = (w & 1) << 5;            // 0,32

    wmma::fragment<wmma::accumulator, 16, 16, 16, float> c0, c1;
    wmma::fill_fragment(c0, 0.0f);
    wmma::fill_fragment(c1, 0.0f);
    wmma::fragment<wmma::matrix_a, 16, 16, 16, __half, wmma::row_major> a;
    wmma::fragment<wmma::matrix_b, 16, 16, 16, __half, wmma::col_major> b0, b1;

    const __half* Ap = A + (size_t)(r0 + trow) * K;
#pragma unroll
    for (int k = 0; k < K; k += 16) {
        wmma::load_matrix_sync(a, Ap + k, K);
        wmma::load_matrix_sync(b0, Wh + (size_t)tcol * K + k, K);
        wmma::load_matrix_sync(b1, Wh + (size_t)(tcol + 16) * K + k, K);
        wmma::mma_sync(c0, a, b0, c0);
        wmma::mma_sync(c1, a, b1, c1);
    }
    wmma::store_matrix_sync(&Cs[trow * CS_LD + tcol],      c0, CS_LD, wmma::mem_row_major);
    wmma::store_matrix_sync(&Cs[trow * CS_LD + tcol + 16], c1, CS_LD, wmma::mem_row_major);
    __syncthreads();

    // Epilogue: each thread handles 16 output elems (quarter row)
    const int lr = threadIdx.x >> 2;          // 0..63
    const int cc = (threadIdx.x & 3) << 4;    // 0,16,32,48
    const int r  = r0 + lr;
    if (r < N_NODES) {
        const float* cp = &Cs[lr * CS_LD + cc];
        __half2 h[8];
#pragma unroll
        for (int j = 0; j < 8; j++) {
            float x = cp[2 * j]     + bias[cc + 2 * j];
            float y = cp[2 * j + 1] + bias[cc + 2 * j + 1];
            h[j] = __floats2half2_rn(x, y);
        }
        uint4* op = (uint4*)(out + (size_t)r * HID + cc);
        op[0] = make_uint4(*(unsigned*)&h[0], *(unsigned*)&h[1],
                           *(unsigned*)&h[2], *(unsigned*)&h[3]);
        op[1] = make_uint4(*(unsigned*)&h[4], *(unsigned*)&h[5],
                           *(unsigned*)&h[6], *(unsigned*)&h[7]);
    }
}

// ---------------------------------------------------------------------------
// CSR build step 1: histogram of row indices (4 edges/thread)
// ---------------------------------------------------------------------------
__global__ void hist_kernel(const int4* __restrict__ rows4, int* __restrict__ cnt) {
    int i = blockIdx.x * blockDim.x + threadIdx.x;
    if (i < N_EDGES / 4) {
        int4 r = rows4[i];
        atomicAdd(&cnt[r.x], 1);
        atomicAdd(&cnt[r.y], 1);
        atomicAdd(&cnt[r.z], 1);
        atomicAdd(&cnt[r.w], 1);
    }
}

// CSR build step 2a: per-block exclusive scan (in place), emit block sums
__global__ void scan_block_kernel(int* __restrict__ data, int* __restrict__ bsums) {
    __shared__ int sh[SCAN_BLK];
    int i = blockIdx.x * SCAN_BLK + threadIdx.x;
    int v = (i < N_NODES) ? data[i] : 0;
    sh[threadIdx.x] = v;
    __syncthreads();
    for (int d = 1; d < SCAN_BLK; d <<= 1) {
        int t = (threadIdx.x >= d) ? sh[threadIdx.x - d] : 0;
        __syncthreads();
        sh[threadIdx.x] += t;
        __syncthreads();
    }
    if (i < N_NODES) data[i] = sh[threadIdx.x] - v;   // exclusive
    if (threadIdx.x == SCAN_BLK - 1) bsums[blockIdx.x] = sh[SCAN_BLK - 1];
}

// CSR build step 2b: exclusive scan of the block sums (single block)
__global__ void scan_top_kernel(int* __restrict__ bsums) {
    __shared__ int sh[128];
    int v = (threadIdx.x < N_SCAN_BLOCKS) ? bsums[threadIdx.x] : 0;
    sh[threadIdx.x] = v;
    __syncthreads();
    for (int d = 1; d < 128; d <<= 1) {
        int t = (threadIdx.x >= d) ? sh[threadIdx.x - d] : 0;
        __syncthreads();
        sh[threadIdx.x] += t;
        __syncthreads();
    }
    if (threadIdx.x < N_SCAN_BLOCKS) bsums[threadIdx.x] = sh[threadIdx.x] - v;
}

// CSR build step 2c: add block offsets, init scatter cursors, seal tail
__global__ void add_off_kernel(int* __restrict__ data, const int* __restrict__ bsums,
                               int* __restrict__ pos) {
    int i = blockIdx.x * blockDim.x + threadIdx.x;
    if (i < N_NODES) {
        int o = data[i] + bsums[i >> 10];
        data[i] = o;
        pos[i] = o;
    }
    if (i == 0) data[N_NODES] = N_EDGES;
}

// CSR build step 3: scatter edges into CSR order (4 edges/thread)
__global__ void scatter_kernel(const int4* __restrict__ rows4,
                               const int4* __restrict__ cols4,
                               const float4* __restrict__ vals4,
                               int* __restrict__ pos, int2* __restrict__ edge) {
    int i = blockIdx.x * blockDim.x + threadIdx.x;
    if (i >= N_EDGES / 4) return;
    int4 r = rows4[i];
    int4 c = cols4[i];
    float4 v = vals4[i];
    int p;
    p = atomicAdd(&pos[r.x], 1); edge[p] = make_int2(c.x, __float_as_int(v.x));
    p = atomicAdd(&pos[r.y], 1); edge[p] = make_int2(c.y, __float_as_int(v.y));
    p = atomicAdd(&pos[r.z], 1); edge[p] = make_int2(c.z, __float_as_int(v.z));
    p = atomicAdd(&pos[r.w], 1); edge[p] = make_int2(c.w, __float_as_int(v.w));
}

// ---------------------------------------------------------------------------
// CSR SpMM with fused ReLU: out[r,:] = relu(sum_e val * H[col,:])
// 4 rows per warp, 8 lanes per row, uint4 (8 fp16 ch) per lane. width-8 shfl
// broadcasts; HFMA2 fp16 accumulation.
// ---------------------------------------------------------------------------
__global__ void spmm_csr_kernel(const int* __restrict__ off,
                                const int2* __restrict__ edge,
                                const __half* __restrict__ H,
                                __half* __restrict__ out) {
    const int lane = threadIdx.x & 31;
    const int hl   = lane & 7;                // lane within 8-lane group
    const int warp = threadIdx.x >> 5;
    const int r = (blockIdx.x * (blockDim.x >> 5) + warp) * 4 + (lane >> 3);
    // grid sized so r < N_NODES always (100000 = 3125 * 32)

    const int s = off[r];
    const int e = off[r + 1];
    int nIter = (e - s + 7) >> 3;
    nIter = max(nIter, __shfl_xor_sync(0xffffffffu, nIter, 8));
    nIter = max(nIter, __shfl_xor_sync(0xffffffffu, nIter, 16));

    __half2 acc0 = __float2half2_rn(0.f);
    __half2 acc1 = acc0, acc2 = acc0, acc3 = acc0;

    for (int it = 0; it < nIter; it++) {
        int idx = s + (it << 3) + hl;
        int2 ev = (idx < e) ? edge[idx] : make_int2(0, 0);   // val=0 -> no-op
#pragma unroll
        for (int j = 0; j < 8; j++) {
            int   c = __shfl_sync(0xffffffffu, ev.x, j, 8);
            float v = __int_as_float(__shfl_sync(0xffffffffu, ev.y, j, 8));
            __half2 vv = __floats2half2_rn(v, v);
            uint4 raw = *((const uint4*)(H + (size_t)c * HID) + hl);
            acc0 = __hfma2(*(__half2*)&raw.x, vv, acc0);
            acc1 = __hfma2(*(__half2*)&raw.y, vv, acc1);
            acc2 = __hfma2(*(__half2*)&raw.z, vv, acc2);
            acc3 = __hfma2(*(__half2*)&raw.w, vv, acc3);
        }
    }

    const __half2 z = __float2half2_rn(0.f);
    acc0 = __hmax2(acc0, z);
    acc1 = __hmax2(acc1, z);
    acc2 = __hmax2(acc2, z);
    acc3 = __hmax2(acc3, z);
    uint4 o;
    o.x = *(unsigned*)&acc0; o.y = *(unsigned*)&acc1;
    o.z = *(unsigned*)&acc2; o.w = *(unsigned*)&acc3;
    *((uint4*)(out + (size_t)r * HID) + hl) = o;
}

// ---------------------------------------------------------------------------
// Global mean pool, partials: 4 blocks per graph, raw sums via atomics.
// ---------------------------------------------------------------------------
__global__ void pool_kernel(const __half* __restrict__ X1,
                            const __half* __restrict__ X2,
                            const __half* __restrict__ X3,
                            const int* __restrict__ batch,
                            float* __restrict__ pool) {
    const int g = blockIdx.x >> 2;
    const int part = blockIdx.x & 3;
    __shared__ int bnd[2];
    if (threadIdx.x < 2) {
        int target = g + threadIdx.x;
        int lo = 0, hi = N_NODES;
        while (lo < hi) { int m = (lo + hi) >> 1; if (batch[m] < target) lo = m + 1; else hi = m; }
        bnd[threadIdx.x] = lo;
    }
    __syncthreads();
    const int gs = bnd[0], ge = bnd[1];
    const int len = ge - gs;
    const int s0 = gs + ((len * part) >> 2);
    const int s1 = gs + ((len * (part + 1)) >> 2);

    const int lane = threadIdx.x & 31;
    const int w = threadIdx.x >> 5;          // 8 warps

    float2 acc = make_float2(0.0f, 0.0f);
    for (int i = s0 + w; i < s1; i += 8) {
        size_t o = (size_t)i * HID;
        float2 a = __half22float2(((const __half2*)(X1 + o))[lane]);
        float2 b = __half22float2(((const __half2*)(X2 + o))[lane]);
        float2 c = __half22float2(((const __half2*)(X3 + o))[lane]);
        acc.x += a.x + b.x + c.x;
        acc.y += a.y + b.y + c.y;
    }

    __shared__ float2 sh[8][32];
    sh[w][lane] = acc;
    __syncthreads();
    if (w == 0) {
        float2 t = sh[0][lane];
#pragma unroll
        for (int k = 1; k < 8; k++) { t.x += sh[k][lane].x; t.y += sh[k][lane].y; }
        atomicAdd(&pool[g * HID + 2 * lane],     t.x);
        atomicAdd(&pool[g * HID + 2 * lane + 1], t.y);
    }
}

// ---------------------------------------------------------------------------
// Head: scale pooled sums, linear + softmax. One thread per graph.
// ---------------------------------------------------------------------------
__global__ void head_kernel(const float* __restrict__ pool,
                            const int* __restrict__ batch,
                            const float* __restrict__ Wout,
                            const float* __restrict__ bout,
                            float* __restrict__ out) {
    int g = threadIdx.x;
    if (g >= N_GRAPHS) return;

    int lo = 0, hi = N_NODES;
    while (lo < hi) { int m = (lo + hi) >> 1; if (batch[m] < g) lo = m + 1; else hi = m; }
    int s0 = lo;
    lo = 0; hi = N_NODES;
    while (lo < hi) { int m = (lo + hi) >> 1; if (batch[m] < g + 1) lo = m + 1; else hi = m; }
    float cnt = fmaxf((float)(lo - s0), 1.0f);
    float sc = 1.0f / (3.0f * cnt);

    float logits[OUT_DIM];
    float mx = -3.0e38f;
#pragma unroll
    for (int j = 0; j < OUT_DIM; j++) {
        float s = bout[j];
        for (int k = 0; k < HID; k++)
            s += pool[g * HID + k] * sc * Wout[j * HID + k];
        logits[j] = s;
        mx = fmaxf(mx, s);
    }
    float sum = 0.0f;
#pragma unroll
    for (int j = 0; j < OUT_DIM; j++) {
        float e = expf(logits[j] - mx);
        logits[j] = e;
        sum += e;
    }
    float isum = 1.0f / sum;
#pragma unroll
    for (int j = 0; j < OUT_DIM; j++)
        out[g * OUT_DIM + j] = logits[j] * isum;
}

// ---------------------------------------------------------------------------
extern "C" void kernel_launch(void* const* d_in, const int* in_sizes, int n_in,
                              void* d_out, int out_size) {
    const float* X    = (const float*)d_in[0];
    const float* vals = (const float*)d_in[1];
    const float* W1   = (const float*)d_in[2];
    const float* b1   = (const float*)d_in[3];
    const float* W2   = (const float*)d_in[4];
    const float* b2   = (const float*)d_in[5];
    const float* W3   = (const float*)d_in[6];
    const float* b3   = (const float*)d_in[7];
    const float* Wout = (const float*)d_in[8];
    const float* bout = (const float*)d_in[9];
    const int* rows   = (const int*)d_in[10];
    const int* cols   = (const int*)d_in[11];
    const int* batch  = (const int*)d_in[12];
    float* out = (float*)d_out;

    void *pOff, *pPos, *pPsum, *pEdge, *pXh, *pW1h, *pW2h, *pW3h;
    void *pT, *p1, *p2, *p3, *pp;
    cudaGetSymbolAddress(&pOff,  g_off);
    cudaGetSymbolAddress(&pPos,  g_pos);
    cudaGetSymbolAddress(&pPsum, g_psum);
    cudaGetSymbolAddress(&pEdge, g_edge);
    cudaGetSymbolAddress(&pXh,  g_Xh);
    cudaGetSymbolAddress(&pW1h, g_W1h);
    cudaGetSymbolAddress(&pW2h, g_W2h);
    cudaGetSymbolAddress(&pW3h, g_W3h);
    cudaGetSymbolAddress(&pT, g_T);
    cudaGetSymbolAddress(&p1, g_X1h);
    cudaGetSymbolAddress(&p2, g_X2h);
    cudaGetSymbolAddress(&p3, g_X3h);
    cudaGetSymbolAddress(&pp, g_pool);

    // Side stream + fork/join events (created once; creation changes no
    // per-call work, and all per-call work is identical & deterministic)
    static cudaStream_t s1 = nullptr;
    static cudaEvent_t evFork = nullptr, evCsr = nullptr;
    if (!s1) {
        cudaStreamCreateWithFlags(&s1, cudaStreamNonBlocking);
        cudaEventCreateWithFlags(&evFork, cudaEventDisableTiming);
        cudaEventCreateWithFlags(&evCsr,  cudaEventDisableTiming);
    }

    const int e4grid = (N_EDGES / 4 + 255) / 256;     // 3125
    const int gemm_grid = NPAD / 64;                  // 1563
    const int spmm_grid = N_NODES / 32;               // 3125 (8 warps x 4 rows)
    const int cx_grid = (NPAD * IN_DIM / 4 + 255) / 256;

    // ---- Fork: CSR build on side stream s1 ----
    cudaEventRecord(evFork, 0);
    cudaStreamWaitEvent(s1, evFork, 0);

    cudaMemsetAsync(pOff, 0, (size_t)(N_NODES + 1) * sizeof(int), s1);
    cudaMemsetAsync(pp, 0, (size_t)N_GRAPHS * HID * sizeof(float), s1);
    hist_kernel<<<e4grid, 256, 0, s1>>>((const int4*)rows, (int*)pOff);
    scan_block_kernel<<<N_SCAN_BLOCKS, SCAN_BLK, 0, s1>>>((int*)pOff, (int*)pPsum);
    scan_top_kernel<<<1, 128, 0, s1>>>((int*)pPsum);
    add_off_kernel<<<(N_NODES + 255) / 256, 256, 0, s1>>>((int*)pOff, (int*)pPsum, (int*)pPos);
    scatter_kernel<<<e4grid, 256, 0, s1>>>((const int4*)rows, (const int4*)cols,
                                           (const float4*)vals, (int*)pPos, (int2*)pEdge);
    cudaEventRecord(evCsr, s1);

    // ---- Main stream: dense prologue (independent of CSR) ----
    convert_x_kernel<<<cx_grid, 256>>>((const float4*)X, (uint2*)pXh);
    convert_w_kernel<<<32, 256>>>(W1, W2, W3, (__half*)pW1h, (__half*)pW2h, (__half*)pW3h);
    linear_wmma_kernel<IN_DIM><<<gemm_grid, 256>>>((const __half*)pXh, (const __half*)pW1h, b1, (__half*)pT);

    // ---- Join: SpMM needs CSR ----
    cudaStreamWaitEvent(0, evCsr, 0);

    // Layer 1 aggregate
    spmm_csr_kernel<<<spmm_grid, 256>>>((int*)pOff, (const int2*)pEdge, (const __half*)pT, (__half*)p1);
    // Layer 2
    linear_wmma_kernel<HID><<<gemm_grid, 256>>>((const __half*)p1, (const __half*)pW2h, b2, (__half*)pT);
    spmm_csr_kernel<<<spmm_grid, 256>>>((int*)pOff, (const int2*)pEdge, (const __half*)pT, (__half*)p2);
    // Layer 3
    linear_wmma_kernel<HID><<<gemm_grid, 256>>>((const __half*)p2, (const __half*)pW3h, b3, (__half*)pT);
    spmm_csr_kernel<<<spmm_grid, 256>>>((int*)pOff, (const int2*)pEdge, (const __half*)pT, (__half*)p3);
    // Pool + head
    pool_kernel<<<N_GRAPHS * 4, 256>>>((const __half*)p1, (const __half*)p2, (const __half*)p3, batch, (float*)pp);
    head_kernel<<<1, 64>>>((float*)pp, batch, Wout, bout, out);
}